// round 6
// baseline (speedup 1.0000x reference)
#include <cuda_runtime.h>

#define S_LEN 2048
#define DM    4096
#define NH    32
#define HD    128
#define WIN   1024

// Scratch (allocation-free rule: __device__ globals, referenced directly
// from device code — no cudaGetSymbolAddress in the captured launch path)
__device__ float g_q[S_LEN * DM];
__device__ float g_k[S_LEN * DM];
__device__ float g_v[S_LEN * DM];
__device__ float g_a[S_LEN * DM];

// ---------------------------------------------------------------------------
// C[M,N] = A[M,K] @ B[N,K]^T   (fp32, 128x128 block, 8x8 per thread, BK=16)
// WHICH selects the scratch buffers: 0: C=g_q, 1: C=g_k, 2: C=g_v,
// 3: A=g_a (C = external out).
// ---------------------------------------------------------------------------
template <int WHICH>
__global__ __launch_bounds__(256, 2) void gemm_abt(
    const float* __restrict__ Aext, const float* __restrict__ B,
    float* __restrict__ Cext, int M, int N, int K)
{
    const float* A = (WHICH == 3) ? (const float*)g_a : Aext;
    float* C = (WHICH == 0) ? g_q : (WHICH == 1) ? g_k
             : (WHICH == 2) ? g_v : Cext;

    __shared__ float As[16][132];   // +4 pad: 2-way max on stores, f4-aligned rows
    __shared__ float Bs[16][132];

    const int bm  = blockIdx.y * 128;
    const int bn  = blockIdx.x * 128;
    const int tid = threadIdx.x;
    const int ty  = tid >> 4;       // 0..15
    const int tx  = tid & 15;       // 0..15

    float acc[8][8];
#pragma unroll
    for (int i = 0; i < 8; i++)
#pragma unroll
        for (int j = 0; j < 8; j++) acc[i][j] = 0.0f;

    for (int k0 = 0; k0 < K; k0 += 16) {
#pragma unroll
        for (int l = 0; l < 2; l++) {
            int idx = tid + (l << 8);           // 0..511
            int r   = idx >> 2;                 // 0..127
            int kq  = (idx & 3) << 2;           // 0,4,8,12
            float4 a4 = *(const float4*)(A + (size_t)(bm + r) * K + k0 + kq);
            As[kq + 0][r] = a4.x; As[kq + 1][r] = a4.y;
            As[kq + 2][r] = a4.z; As[kq + 3][r] = a4.w;
            float4 b4 = *(const float4*)(B + (size_t)(bn + r) * K + k0 + kq);
            Bs[kq + 0][r] = b4.x; Bs[kq + 1][r] = b4.y;
            Bs[kq + 2][r] = b4.z; Bs[kq + 3][r] = b4.w;
        }
        __syncthreads();

#pragma unroll
        for (int k = 0; k < 16; k++) {
            float a[8], b[8];
#pragma unroll
            for (int i = 0; i < 8; i++) a[i] = As[k][ty * 8 + i];
#pragma unroll
            for (int j = 0; j < 8; j++) b[j] = Bs[k][tx * 8 + j];
#pragma unroll
            for (int i = 0; i < 8; i++)
#pragma unroll
                for (int j = 0; j < 8; j++)
                    acc[i][j] = fmaf(a[i], b[j], acc[i][j]);
        }
        __syncthreads();
    }

#pragma unroll
    for (int i = 0; i < 8; i++) {
        float* cr = C + (size_t)(bm + ty * 8 + i) * N + bn + tx * 8;
        float4 c0 = {acc[i][0], acc[i][1], acc[i][2], acc[i][3]};
        float4 c1 = {acc[i][4], acc[i][5], acc[i][6], acc[i][7]};
        *(float4*)cr       = c0;
        *(float4*)(cr + 4) = c1;
    }
}

// ---------------------------------------------------------------------------
// RoPE, in place on g_q and g_k (layout [S, H*D]); one thread per (s, h, d<64)
// ---------------------------------------------------------------------------
__global__ void rope_kernel()
{
    int idx = blockIdx.x * blockDim.x + threadIdx.x;   // S*H*64 = 4194304
    int d = idx & 63;
    int s = idx >> 11;

    // inv_freq[j] = 1 / 10000^{(2j)/128} = 2^{-(2j/128)*log2(10000)}
    const float LOG2_10000 = 13.287712379549449f;
    float ex   = (float)(2 * d) * (1.0f / 128.0f);
    float invf = exp2f(-ex * LOG2_10000);
    float ang  = (float)s * invf;
    float cv = cosf(ang);
    float sv = sinf(ang);

    int h = (idx >> 6) & 31;
    size_t base = (size_t)s * DM + h * HD + d;
    float q1 = g_q[base], q2 = g_q[base + 64];
    g_q[base]      = q1 * cv - q2 * sv;
    g_q[base + 64] = q2 * cv + q1 * sv;
    float k1 = g_k[base], k2 = g_k[base + 64];
    g_k[base]      = k1 * cv - k2 * sv;
    g_k[base + 64] = k2 * cv + k1 * sv;
}

// ---------------------------------------------------------------------------
// Flash attention, causal sliding window (W=1024), fp32, g_q/g_k/g_v -> g_a.
// Block = (q-tile of 128 rows, head). 256 threads:
//   tr = tid/16 -> rows tr*8..tr*8+7
//   tc = tid%16 -> score cols {tc, tc+16, tc+32, tc+48}, O cols tc*8..tc*8+7
// K tile XOR-swizzled at float4 granularity: slot = row*32 + (d4 ^ (row&7))
// -> same-row lanes (consecutive K rows) hit distinct 16B bank groups.
// ---------------------------------------------------------------------------
#define ATTN_SMEM_FLOATS (128 * 128 + 64 * 128 + 64 * 128 + 128 * 64)
#define ATTN_SMEM_BYTES  (ATTN_SMEM_FLOATS * 4)

__global__ __launch_bounds__(256, 1) void attn_kernel()
{
    extern __shared__ float sm[];
    float* Qs = sm;                 // [128][128]
    float* Ks = Qs + 128 * 128;     // [64][128]  swizzled
    float* Vs = Ks + 64 * 128;      // [64][128]
    float* Ps = Vs + 64 * 128;      // [128][64]

    const int qtb = blockIdx.x;     // 0..15
    const int h   = blockIdx.y;     // 0..31
    const int q0  = qtb * 128;
    const int tid = threadIdx.x;
    const int tr  = tid >> 4;
    const int tc  = tid & 15;
    const float scale = 0.08838834764831845f;  // 1/sqrt(128)

    // Load + pre-scale Q tile
    for (int l = tid; l < 4096; l += 256) {
        int row = l >> 5, d4 = l & 31;
        float4 v = *(const float4*)(g_q + (size_t)(q0 + row) * DM + h * HD + (d4 << 2));
        v.x *= scale; v.y *= scale; v.z *= scale; v.w *= scale;
        *(float4*)(Qs + row * 128 + (d4 << 2)) = v;
    }

    float m[8], lsum[8], o[8][8];
#pragma unroll
    for (int i = 0; i < 8; i++) {
        m[i] = -3.0e38f; lsum[i] = 0.0f;
#pragma unroll
        for (int c = 0; c < 8; c++) o[i][c] = 0.0f;
    }

    int kb_lo = 2 * qtb - 16; if (kb_lo < 0) kb_lo = 0;
    const int kb_hi = 2 * qtb + 1;

    for (int kb = kb_lo; kb <= kb_hi; kb++) {
        const int k0 = kb * 64;
        __syncthreads();
        // Load K (swizzled) + V tiles
        for (int l = tid; l < 2048; l += 256) {
            int row = l >> 5, d4 = l & 31;
            float4 kv = *(const float4*)(g_k + (size_t)(k0 + row) * DM + h * HD + (d4 << 2));
            *(float4*)(Ks + row * 128 + ((d4 ^ (row & 7)) << 2)) = kv;
            float4 vv = *(const float4*)(g_v + (size_t)(k0 + row) * DM + h * HD + (d4 << 2));
            *(float4*)(Vs + row * 128 + (d4 << 2)) = vv;
        }
        __syncthreads();

        // ---- scores: s[8 rows][4 cols], col j -> global col k0 + tc + 16j
        float s[8][4];
#pragma unroll
        for (int i = 0; i < 8; i++)
#pragma unroll
            for (int j = 0; j < 4; j++) s[i][j] = 0.0f;

#pragma unroll 4
        for (int d4 = 0; d4 < 32; d4++) {
            float4 kf[4];
#pragma unroll
            for (int j = 0; j < 4; j++) {
                int col = tc + (j << 4);
                kf[j] = *(const float4*)(Ks + col * 128 + ((d4 ^ (tc & 7)) << 2));
            }
#pragma unroll
            for (int i = 0; i < 8; i++) {
                float4 qf = *(const float4*)(Qs + (tr * 8 + i) * 128 + (d4 << 2));
#pragma unroll
                for (int j = 0; j < 4; j++) {
                    s[i][j] = fmaf(qf.x, kf[j].x, s[i][j]);
                    s[i][j] = fmaf(qf.y, kf[j].y, s[i][j]);
                    s[i][j] = fmaf(qf.z, kf[j].z, s[i][j]);
                    s[i][j] = fmaf(qf.w, kf[j].w, s[i][j]);
                }
            }
        }

        // ---- mask + online softmax (16-lane row groups)
#pragma unroll
        for (int i = 0; i < 8; i++) {
            const int gi = q0 + tr * 8 + i;
            float tmax = -3.0e38f;
#pragma unroll
            for (int j = 0; j < 4; j++) {
                int gj = k0 + tc + (j << 4);
                if (gj > gi || gj + WIN <= gi) s[i][j] = -3.0e38f;
                tmax = fmaxf(tmax, s[i][j]);
            }
#pragma unroll
            for (int off = 8; off > 0; off >>= 1)
                tmax = fmaxf(tmax, __shfl_xor_sync(0xffffffffu, tmax, off));
            float mnew = fmaxf(m[i], tmax);
            float corr = expf(m[i] - mnew);
            float rs = 0.0f;
#pragma unroll
            for (int j = 0; j < 4; j++) {
                float p = expf(s[i][j] - mnew);
                Ps[(tr * 8 + i) * 64 + tc + (j << 4)] = p;
                rs += p;
            }
#pragma unroll
            for (int off = 8; off > 0; off >>= 1)
                rs += __shfl_xor_sync(0xffffffffu, rs, off);
            m[i]    = mnew;
            lsum[i] = lsum[i] * corr + rs;
#pragma unroll
            for (int c = 0; c < 8; c++) o[i][c] *= corr;
        }
        __syncthreads();

        // ---- PV: O[row][tc*8+c] += P[row][k] * V[k][tc*8+c]
        for (int k4 = 0; k4 < 64; k4 += 4) {
            float4 pf[8];
#pragma unroll
            for (int i = 0; i < 8; i++)
                pf[i] = *(const float4*)(Ps + (tr * 8 + i) * 64 + k4);
#pragma unroll
            for (int kk = 0; kk < 4; kk++) {
                const float* vr = Vs + (k4 + kk) * 128 + (tc << 3);
                float4 v0 = *(const float4*)vr;
                float4 v1 = *(const float4*)(vr + 4);
#pragma unroll
                for (int i = 0; i < 8; i++) {
                    float p = (kk == 0) ? pf[i].x : (kk == 1) ? pf[i].y
                            : (kk == 2) ? pf[i].z : pf[i].w;
                    o[i][0] = fmaf(p, v0.x, o[i][0]);
                    o[i][1] = fmaf(p, v0.y, o[i][1]);
                    o[i][2] = fmaf(p, v0.z, o[i][2]);
                    o[i][3] = fmaf(p, v0.w, o[i][3]);
                    o[i][4] = fmaf(p, v1.x, o[i][4]);
                    o[i][5] = fmaf(p, v1.y, o[i][5]);
                    o[i][6] = fmaf(p, v1.z, o[i][6]);
                    o[i][7] = fmaf(p, v1.w, o[i][7]);
                }
            }
        }
    }

    // ---- epilogue: normalize and store [S, H*D] into g_a
#pragma unroll
    for (int i = 0; i < 8; i++) {
        float inv = 1.0f / lsum[i];
        float* orow = g_a + (size_t)(q0 + tr * 8 + i) * DM + h * HD + (tc << 3);
        float4 r0 = {o[i][0] * inv, o[i][1] * inv, o[i][2] * inv, o[i][3] * inv};
        float4 r1 = {o[i][4] * inv, o[i][5] * inv, o[i][6] * inv, o[i][7] * inv};
        *(float4*)orow       = r0;
        *(float4*)(orow + 4) = r1;
    }
}

// ---------------------------------------------------------------------------
extern "C" void kernel_launch(void* const* d_in, const int* in_sizes, int n_in,
                              void* d_out, int out_size)
{
    (void)in_sizes; (void)n_in; (void)out_size;
    const float* x  = (const float*)d_in[0];
    const float* Wq = (const float*)d_in[1];
    const float* Wk = (const float*)d_in[2];
    const float* Wv = (const float*)d_in[3];
    const float* Wo = (const float*)d_in[4];
    float* out = (float*)d_out;

    dim3 gproj(DM / 128, S_LEN / 128);   // (32, 16)

    gemm_abt<0><<<gproj, 256>>>(x, Wq, nullptr, S_LEN, DM, DM);
    gemm_abt<1><<<gproj, 256>>>(x, Wk, nullptr, S_LEN, DM, DM);
    gemm_abt<2><<<gproj, 256>>>(x, Wv, nullptr, S_LEN, DM, DM);

    rope_kernel<<<(S_LEN * NH * 64) / 256, 256>>>();

    cudaFuncSetAttribute(attn_kernel,
                         cudaFuncAttributeMaxDynamicSharedMemorySize,
                         ATTN_SMEM_BYTES);
    attn_kernel<<<dim3(S_LEN / 128, NH), 256, ATTN_SMEM_BYTES>>>();

    gemm_abt<3><<<gproj, 256>>>(nullptr, Wo, out, S_LEN, DM, DM);
}

// round 8
// speedup vs baseline: 2.4379x; 2.4379x over previous
#include <cuda_runtime.h>
#include <cuda_bf16.h>
#include <cstdint>

#define S_LEN 2048
#define DM    4096
#define NH    32
#define HD    128
#define WIN   1024

// ---------------- scratch (__device__ globals; no allocation APIs) ----------
__device__ float g_q[S_LEN * DM];
__device__ float g_k[S_LEN * DM];
__device__ float g_v[S_LEN * DM];
__device__ float g_a[S_LEN * DM];

__device__ __nv_bfloat16 d_xh[S_LEN * DM], d_xl[S_LEN * DM];   // x split
__device__ __nv_bfloat16 d_ah[S_LEN * DM], d_al[S_LEN * DM];   // attn-out split
__device__ __nv_bfloat16 d_wh[4][DM * DM], d_wl[4][DM * DM];   // Wq,Wk,Wv,Wo

// ---------------- PTX helpers (sm_80-class only: ldmatrix / mma / cp.async) -
__device__ __forceinline__ uint32_t s2u(const void* p) {
    uint32_t r;
    asm("{ .reg .u64 t; cvta.to.shared.u64 t, %1; cvt.u32.u64 %0, t; }"
        : "=r"(r) : "l"(p));
    return r;
}
#define LDSM4(r0, r1, r2, r3, addr) \
    asm volatile("ldmatrix.sync.aligned.m8n8.x4.shared.b16 {%0,%1,%2,%3}, [%4];" \
        : "=r"(r0), "=r"(r1), "=r"(r2), "=r"(r3) : "r"(addr))
__device__ __forceinline__ void mma16816(float* c, const uint32_t* a, const uint32_t* b) {
    asm volatile(
        "mma.sync.aligned.m16n8k16.row.col.f32.bf16.bf16.f32 "
        "{%0,%1,%2,%3}, {%4,%5,%6,%7}, {%8,%9}, {%0,%1,%2,%3};"
        : "+f"(c[0]), "+f"(c[1]), "+f"(c[2]), "+f"(c[3])
        : "r"(a[0]), "r"(a[1]), "r"(a[2]), "r"(a[3]), "r"(b[0]), "r"(b[1]));
}
#define CPA16(dst, src) \
    asm volatile("cp.async.cg.shared.global [%0], [%1], 16;" :: "r"(dst), "l"(src))
#define CPC() asm volatile("cp.async.commit_group;")
#define CPW1() asm volatile("cp.async.wait_group 1;")
#define CPW0() asm volatile("cp.async.wait_group 0;")

// 16B-chunk XOR swizzle inside a [rows][4-chunk] tile (8 KB for 128 rows)
__device__ __forceinline__ uint32_t tile_off(int row, int ck) {
    return (uint32_t)(((row << 2) + (ck ^ ((row >> 1) & 3))) << 4);
}

// ---------------------------------------------------------------------------
// Split fp32 -> bf16 hi/lo pairs.  DST: 0=x, 1..4=Wq..Wo, 5=g_a
// ---------------------------------------------------------------------------
template <int DST>
__global__ void split_kernel(const float* __restrict__ src)
{
    const float* s = (DST == 5) ? (const float*)g_a : src;
    __nv_bfloat16* hi = (DST == 0) ? d_xh : (DST == 5) ? d_ah : d_wh[DST - 1];
    __nv_bfloat16* lo = (DST == 0) ? d_xl : (DST == 5) ? d_al : d_wl[DST - 1];

    int i4 = blockIdx.x * blockDim.x + threadIdx.x;
    float4 v = ((const float4*)s)[i4];
    __nv_bfloat16 h0 = __float2bfloat16(v.x);
    __nv_bfloat16 h1 = __float2bfloat16(v.y);
    __nv_bfloat16 h2 = __float2bfloat16(v.z);
    __nv_bfloat16 h3 = __float2bfloat16(v.w);
    __nv_bfloat16 l0 = __float2bfloat16(v.x - __bfloat162float(h0));
    __nv_bfloat16 l1 = __float2bfloat16(v.y - __bfloat162float(h1));
    __nv_bfloat16 l2 = __float2bfloat16(v.z - __bfloat162float(h2));
    __nv_bfloat16 l3 = __float2bfloat16(v.w - __bfloat162float(h3));
    ((__nv_bfloat162*)hi)[i4 * 2 + 0] = __halves2bfloat162(h0, h1);
    ((__nv_bfloat162*)hi)[i4 * 2 + 1] = __halves2bfloat162(h2, h3);
    ((__nv_bfloat162*)lo)[i4 * 2 + 0] = __halves2bfloat162(l0, l1);
    ((__nv_bfloat162*)lo)[i4 * 2 + 1] = __halves2bfloat162(l2, l3);
}

// ---------------------------------------------------------------------------
// mma.sync bf16-split GEMM: C[M,N] = A[M,K] @ B[N,K]^T, fp32 accuracy via
// 3 products (hh + hl + lh).  BM=BN=128, BK=32, 256 thr, cp.async 2-stage.
// WHICH: 0 x@WqT->g_q, 1 x@WkT->g_k, 2 x@WvT->g_v, 3 a@WoT->Cext
// Smem buffer b at b*32768: Ah +0, Al +8192, Bh +16384, Bl +24576 (8 KB each)
// ---------------------------------------------------------------------------
#define GEMM_SMEM (2 * 32768)

template <int WHICH>
__global__ __launch_bounds__(256) void gemm_mma(float* __restrict__ Cext)
{
    const __nv_bfloat16* Ah = (WHICH == 3) ? d_ah : d_xh;
    const __nv_bfloat16* Al = (WHICH == 3) ? d_al : d_xl;
    const __nv_bfloat16* Bh = d_wh[WHICH];
    const __nv_bfloat16* Bl = d_wl[WHICH];
    float* C = (WHICH == 0) ? g_q : (WHICH == 1) ? g_k
             : (WHICH == 2) ? g_v : Cext;

    extern __shared__ __align__(16) char smraw[];
    const uint32_t sb = s2u(smraw);

    const int tid  = threadIdx.x;
    const int lane = tid & 31;
    const int warp = tid >> 5;
    const int wm   = warp & 1;        // 2 m-tiles of 64
    const int wn   = warp >> 1;       // 4 n-tiles of 32
    const int bm   = blockIdx.y * 128;
    const int bn   = blockIdx.x * 128;

    float acc[16][4];
#pragma unroll
    for (int i = 0; i < 16; i++)
#pragma unroll
        for (int j = 0; j < 4; j++) acc[i][j] = 0.0f;

    // per-thread copy chunks: cid = tid + t*256 -> row = cid>>2, ck = cid&3
#define PREFETCH(kt, bi)                                                        \
    do {                                                                        \
        const int k0_ = (kt) * 32;                                              \
        const uint32_t bufb_ = sb + (bi) * 32768;                               \
        _Pragma("unroll")                                                       \
        for (int t_ = 0; t_ < 2; t_++) {                                        \
            int cid_ = tid + t_ * 256;                                          \
            int row_ = cid_ >> 2, ck_ = cid_ & 3;                               \
            uint32_t so_ = tile_off(row_, ck_);                                 \
            size_t ga_ = (size_t)(bm + row_) * DM + k0_ + ck_ * 8;              \
            size_t gb_ = (size_t)(bn + row_) * DM + k0_ + ck_ * 8;              \
            CPA16(bufb_ + so_,          Ah + ga_);                              \
            CPA16(bufb_ + 8192 + so_,   Al + ga_);                              \
            CPA16(bufb_ + 16384 + so_,  Bh + gb_);                              \
            CPA16(bufb_ + 24576 + so_,  Bl + gb_);                              \
        }                                                                       \
    } while (0)

    PREFETCH(0, 0);
    CPC();

    const int arow = (lane & 15) + wm * 64;           // + mt*16
    const int acks = (lane >> 4);                     // +2s
    const int bnrw = wn * 32 + (lane & 7) + ((lane >> 4) << 3);  // + p*16
    const int bcks = ((lane >> 3) & 1);               // +2s

    for (int kt = 0; kt < 128; kt++) {
        const int bi = kt & 1;
        if (kt + 1 < 128) {
            PREFETCH(kt + 1, (kt + 1) & 1);
            CPC();
            CPW1();
        } else {
            CPW0();
        }
        __syncthreads();

        const uint32_t bAh = sb + bi * 32768;
        const uint32_t bAl = bAh + 8192;
        const uint32_t bBh = bAh + 16384;
        const uint32_t bBl = bAh + 24576;

#pragma unroll
        for (int s = 0; s < 2; s++) {
            uint32_t ah[4][4], al[4][4], bh[4][2], bl[4][2];
            const int ack = 2 * s + acks;
            const int bck = 2 * s + bcks;
#pragma unroll
            for (int mt = 0; mt < 4; mt++) {
                uint32_t off = tile_off(arow + mt * 16, ack);
                LDSM4(ah[mt][0], ah[mt][1], ah[mt][2], ah[mt][3], bAh + off);
                LDSM4(al[mt][0], al[mt][1], al[mt][2], al[mt][3], bAl + off);
            }
#pragma unroll
            for (int p = 0; p < 2; p++) {
                uint32_t off = tile_off(bnrw + p * 16, bck);
                uint32_t t0, t1, t2, t3;
                LDSM4(t0, t1, t2, t3, bBh + off);
                bh[2 * p][0] = t0; bh[2 * p][1] = t1;
                bh[2 * p + 1][0] = t2; bh[2 * p + 1][1] = t3;
                LDSM4(t0, t1, t2, t3, bBl + off);
                bl[2 * p][0] = t0; bl[2 * p][1] = t1;
                bl[2 * p + 1][0] = t2; bl[2 * p + 1][1] = t3;
            }
#pragma unroll
            for (int mt = 0; mt < 4; mt++)
#pragma unroll
                for (int nt = 0; nt < 4; nt++) {
                    mma16816(acc[mt * 4 + nt], ah[mt], bh[nt]);
                    mma16816(acc[mt * 4 + nt], ah[mt], bl[nt]);
                    mma16816(acc[mt * 4 + nt], al[mt], bh[nt]);
                }
        }
        __syncthreads();
    }

    // epilogue: fragment (t/4, 2*(t%4)) rows +0/+8
#pragma unroll
    for (int mt = 0; mt < 4; mt++)
#pragma unroll
        for (int nt = 0; nt < 4; nt++) {
            int row = bm + wm * 64 + mt * 16 + (lane >> 2);
            int col = bn + wn * 32 + nt * 8 + 2 * (lane & 3);
            float* c0 = C + (size_t)row * DM + col;
            float* c1 = C + (size_t)(row + 8) * DM + col;
            float2 v0 = { acc[mt * 4 + nt][0], acc[mt * 4 + nt][1] };
            float2 v1 = { acc[mt * 4 + nt][2], acc[mt * 4 + nt][3] };
            *(float2*)c0 = v0;
            *(float2*)c1 = v1;
        }
#undef PREFETCH
}

// ---------------------------------------------------------------------------
// RoPE, in place on g_q and g_k
// ---------------------------------------------------------------------------
__global__ void rope_kernel()
{
    int idx = blockIdx.x * blockDim.x + threadIdx.x;
    int d = idx & 63;
    int s = idx >> 11;
    const float LOG2_10000 = 13.287712379549449f;
    float ex   = (float)(2 * d) * (1.0f / 128.0f);
    float invf = exp2f(-ex * LOG2_10000);
    float ang  = (float)s * invf;
    float cv = cosf(ang), sv = sinf(ang);
    int h = (idx >> 6) & 31;
    size_t base = (size_t)s * DM + h * HD + d;
    float q1 = g_q[base], q2 = g_q[base + 64];
    g_q[base]      = q1 * cv - q2 * sv;
    g_q[base + 64] = q2 * cv + q1 * sv;
    float k1 = g_k[base], k2 = g_k[base + 64];
    g_k[base]      = k1 * cv - k2 * sv;
    g_k[base + 64] = k2 * cv + k1 * sv;
}

// ---------------------------------------------------------------------------
// Flash attention (proven R6 version): causal sliding window, fp32 FMA.
// ---------------------------------------------------------------------------
#define ATTN_SMEM_FLOATS (128 * 128 + 64 * 128 + 64 * 128 + 128 * 64)
#define ATTN_SMEM_BYTES  (ATTN_SMEM_FLOATS * 4)

__global__ __launch_bounds__(256, 1) void attn_kernel()
{
    extern __shared__ float sm[];
    float* Qs = sm;
    float* Ks = Qs + 128 * 128;
    float* Vs = Ks + 64 * 128;
    float* Ps = Vs + 64 * 128;

    const int qtb = blockIdx.x;
    const int h   = blockIdx.y;
    const int q0  = qtb * 128;
    const int tid = threadIdx.x;
    const int tr  = tid >> 4;
    const int tc  = tid & 15;
    const float scale = 0.08838834764831845f;

    for (int l = tid; l < 4096; l += 256) {
        int row = l >> 5, d4 = l & 31;
        float4 v = *(const float4*)(g_q + (size_t)(q0 + row) * DM + h * HD + (d4 << 2));
        v.x *= scale; v.y *= scale; v.z *= scale; v.w *= scale;
        *(float4*)(Qs + row * 128 + (d4 << 2)) = v;
    }

    float m[8], lsum[8], o[8][8];
#pragma unroll
    for (int i = 0; i < 8; i++) {
        m[i] = -3.0e38f; lsum[i] = 0.0f;
#pragma unroll
        for (int c = 0; c < 8; c++) o[i][c] = 0.0f;
    }

    int kb_lo = 2 * qtb - 16; if (kb_lo < 0) kb_lo = 0;
    const int kb_hi = 2 * qtb + 1;

    for (int kb = kb_lo; kb <= kb_hi; kb++) {
        const int k0 = kb * 64;
        __syncthreads();
        for (int l = tid; l < 2048; l += 256) {
            int row = l >> 5, d4 = l & 31;
            float4 kv = *(const float4*)(g_k + (size_t)(k0 + row) * DM + h * HD + (d4 << 2));
            *(float4*)(Ks + row * 128 + ((d4 ^ (row & 7)) << 2)) = kv;
            float4 vv = *(const float4*)(g_v + (size_t)(k0 + row) * DM + h * HD + (d4 << 2));
            *(float4*)(Vs + row * 128 + (d4 << 2)) = vv;
        }
        __syncthreads();

        float s[8][4];
#pragma unroll
        for (int i = 0; i < 8; i++)
#pragma unroll
            for (int j = 0; j < 4; j++) s[i][j] = 0.0f;

#pragma unroll 4
        for (int d4 = 0; d4 < 32; d4++) {
            float4 kf[4];
#pragma unroll
            for (int j = 0; j < 4; j++) {
                int col = tc + (j << 4);
                kf[j] = *(const float4*)(Ks + col * 128 + ((d4 ^ (tc & 7)) << 2));
            }
#pragma unroll
            for (int i = 0; i < 8; i++) {
                float4 qf = *(const float4*)(Qs + (tr * 8 + i) * 128 + (d4 << 2));
#pragma unroll
                for (int j = 0; j < 4; j++) {
                    s[i][j] = fmaf(qf.x, kf[j].x, s[i][j]);
                    s[i][j] = fmaf(qf.y, kf[j].y, s[i][j]);
                    s[i][j] = fmaf(qf.z, kf[j].z, s[i][j]);
                    s[i][j] = fmaf(qf.w, kf[j].w, s[i][j]);
                }
            }
        }

#pragma unroll
        for (int i = 0; i < 8; i++) {
            const int gi = q0 + tr * 8 + i;
            float tmax = -3.0e38f;
#pragma unroll
            for (int j = 0; j < 4; j++) {
                int gj = k0 + tc + (j << 4);
                if (gj > gi || gj + WIN <= gi) s[i][j] = -3.0e38f;
                tmax = fmaxf(tmax, s[i][j]);
            }
#pragma unroll
            for (int off = 8; off > 0; off >>= 1)
                tmax = fmaxf(tmax, __shfl_xor_sync(0xffffffffu, tmax, off));
            float mnew = fmaxf(m[i], tmax);
            float corr = expf(m[i] - mnew);
            float rs = 0.0f;
#pragma unroll
            for (int j = 0; j < 4; j++) {
                float p = expf(s[i][j] - mnew);
                Ps[(tr * 8 + i) * 64 + tc + (j << 4)] = p;
                rs += p;
            }
#pragma unroll
            for (int off = 8; off > 0; off >>= 1)
                rs += __shfl_xor_sync(0xffffffffu, rs, off);
            m[i]    = mnew;
            lsum[i] = lsum[i] * corr + rs;
#pragma unroll
            for (int c = 0; c < 8; c++) o[i][c] *= corr;
        }
        __syncthreads();

        for (int k4 = 0; k4 < 64; k4 += 4) {
            float4 pf[8];
#pragma unroll
            for (int i = 0; i < 8; i++)
                pf[i] = *(const float4*)(Ps + (tr * 8 + i) * 64 + k4);
#pragma unroll
            for (int kk = 0; kk < 4; kk++) {
                const float* vr = Vs + (k4 + kk) * 128 + (tc << 3);
                float4 v0 = *(const float4*)vr;
                float4 v1 = *(const float4*)(vr + 4);
#pragma unroll
                for (int i = 0; i < 8; i++) {
                    float p = (kk == 0) ? pf[i].x : (kk == 1) ? pf[i].y
                            : (kk == 2) ? pf[i].z : pf[i].w;
                    o[i][0] = fmaf(p, v0.x, o[i][0]);
                    o[i][1] = fmaf(p, v0.y, o[i][1]);
                    o[i][2] = fmaf(p, v0.z, o[i][2]);
                    o[i][3] = fmaf(p, v0.w, o[i][3]);
                    o[i][4] = fmaf(p, v1.x, o[i][4]);
                    o[i][5] = fmaf(p, v1.y, o[i][5]);
                    o[i][6] = fmaf(p, v1.z, o[i][6]);
                    o[i][7] = fmaf(p, v1.w, o[i][7]);
                }
            }
        }
    }

#pragma unroll
    for (int i = 0; i < 8; i++) {
        float inv = 1.0f / lsum[i];
        float* orow = g_a + (size_t)(q0 + tr * 8 + i) * DM + h * HD + (tc << 3);
        float4 r0 = {o[i][0] * inv, o[i][1] * inv, o[i][2] * inv, o[i][3] * inv};
        float4 r1 = {o[i][4] * inv, o[i][5] * inv, o[i][6] * inv, o[i][7] * inv};
        *(float4*)orow       = r0;
        *(float4*)(orow + 4) = r1;
    }
}

// ---------------------------------------------------------------------------
extern "C" void kernel_launch(void* const* d_in, const int* in_sizes, int n_in,
                              void* d_out, int out_size)
{
    (void)in_sizes; (void)n_in; (void)out_size;
    const float* x  = (const float*)d_in[0];
    const float* Wq = (const float*)d_in[1];
    const float* Wk = (const float*)d_in[2];
    const float* Wv = (const float*)d_in[3];
    const float* Wo = (const float*)d_in[4];
    float* out = (float*)d_out;

    cudaFuncSetAttribute(gemm_mma<0>, cudaFuncAttributeMaxDynamicSharedMemorySize, GEMM_SMEM);
    cudaFuncSetAttribute(gemm_mma<1>, cudaFuncAttributeMaxDynamicSharedMemorySize, GEMM_SMEM);
    cudaFuncSetAttribute(gemm_mma<2>, cudaFuncAttributeMaxDynamicSharedMemorySize, GEMM_SMEM);
    cudaFuncSetAttribute(gemm_mma<3>, cudaFuncAttributeMaxDynamicSharedMemorySize, GEMM_SMEM);
    cudaFuncSetAttribute(attn_kernel, cudaFuncAttributeMaxDynamicSharedMemorySize, ATTN_SMEM_BYTES);

    const int XB = (S_LEN * DM) / 1024;   // 8192 blocks (4 elems/thread)
    const int WB = (DM * DM) / 1024;      // 16384 blocks

    split_kernel<0><<<XB, 256>>>(x);
    split_kernel<1><<<WB, 256>>>(Wq);
    split_kernel<2><<<WB, 256>>>(Wk);
    split_kernel<3><<<WB, 256>>>(Wv);
    split_kernel<4><<<WB, 256>>>(Wo);

    dim3 gg(DM / 128, S_LEN / 128);       // (32, 16)
    gemm_mma<0><<<gg, 256, GEMM_SMEM>>>(nullptr);
    gemm_mma<1><<<gg, 256, GEMM_SMEM>>>(nullptr);
    gemm_mma<2><<<gg, 256, GEMM_SMEM>>>(nullptr);

    rope_kernel<<<(S_LEN * NH * 64) / 256, 256>>>();

    attn_kernel<<<dim3(S_LEN / 128, NH), 256, ATTN_SMEM_BYTES>>>();

    split_kernel<5><<<XB, 256>>>(nullptr);
    gemm_mma<3><<<gg, 256, GEMM_SMEM>>>(out);
}

// round 9
// speedup vs baseline: 2.9409x; 1.2063x over previous
#include <cuda_runtime.h>
#include <cuda_bf16.h>
#include <cstdint>

#define S_LEN 2048
#define DM    4096
#define NH    32
#define HD    128
#define WIN   1024

// ---------------- scratch (__device__ globals; no allocation APIs) ----------
__device__ float g_q[S_LEN * DM];
__device__ float g_k[S_LEN * DM];
__device__ float g_v[S_LEN * DM];
__device__ float g_a[S_LEN * DM];

__device__ __nv_bfloat16 d_xh[S_LEN * DM], d_xl[S_LEN * DM];   // x split
__device__ __nv_bfloat16 d_ah[S_LEN * DM], d_al[S_LEN * DM];   // attn-out split
__device__ __nv_bfloat16 d_wh[4][DM * DM], d_wl[4][DM * DM];   // Wq,Wk,Wv,Wo

// attention operands (bf16 hi/lo)
__device__ __nv_bfloat16 d_qh[S_LEN * DM], d_ql[S_LEN * DM];   // Q (pre-scaled)
__device__ __nv_bfloat16 d_kh2[S_LEN * DM], d_kl2[S_LEN * DM]; // K
__device__ __nv_bfloat16 d_vth[S_LEN * DM], d_vtl[S_LEN * DM]; // V^T [h*128+d][s]

// ---------------- PTX helpers (sm_80-class only) ----------------------------
__device__ __forceinline__ uint32_t s2u(const void* p) {
    uint32_t r;
    asm("{ .reg .u64 t; cvta.to.shared.u64 t, %1; cvt.u32.u64 %0, t; }"
        : "=r"(r) : "l"(p));
    return r;
}
#define LDSM4(r0, r1, r2, r3, addr) \
    asm volatile("ldmatrix.sync.aligned.m8n8.x4.shared.b16 {%0,%1,%2,%3}, [%4];" \
        : "=r"(r0), "=r"(r1), "=r"(r2), "=r"(r3) : "r"(addr))
__device__ __forceinline__ void mma16816(float* c, const uint32_t* a, const uint32_t* b) {
    asm volatile(
        "mma.sync.aligned.m16n8k16.row.col.f32.bf16.bf16.f32 "
        "{%0,%1,%2,%3}, {%4,%5,%6,%7}, {%8,%9}, {%0,%1,%2,%3};"
        : "+f"(c[0]), "+f"(c[1]), "+f"(c[2]), "+f"(c[3])
        : "r"(a[0]), "r"(a[1]), "r"(a[2]), "r"(a[3]), "r"(b[0]), "r"(b[1]));
}
#define CPA16(dst, src) \
    asm volatile("cp.async.cg.shared.global [%0], [%1], 16;" :: "r"(dst), "l"(src))
#define CPC() asm volatile("cp.async.commit_group;")
#define CPW1() asm volatile("cp.async.wait_group 1;")
#define CPW0() asm volatile("cp.async.wait_group 0;")

// 16B-chunk XOR swizzles
__device__ __forceinline__ uint32_t tile_off(int row, int ck) {        // 4 chunks/row
    return (uint32_t)(((row << 2) + (ck ^ ((row >> 1) & 3))) << 4);
}
__device__ __forceinline__ uint32_t swz16(int r, int c) {              // 16 chunks/row
    return (uint32_t)((c & 8) | ((c ^ (r & 7)) & 7));
}
__device__ __forceinline__ uint32_t swz8(int r, int c) {               // 8 chunks/row
    return (uint32_t)(c ^ (r & 7));
}
// pack two fp32 -> bf16x2 hi/lo split
__device__ __forceinline__ void split2(float x, float y, uint32_t& hi, uint32_t& lo) {
    __nv_bfloat16 hx = __float2bfloat16(x), hy = __float2bfloat16(y);
    __nv_bfloat162 hp = __halves2bfloat162(hx, hy);
    hi = *reinterpret_cast<uint32_t*>(&hp);
    __nv_bfloat16 lx = __float2bfloat16(x - __bfloat162float(hx));
    __nv_bfloat16 ly = __float2bfloat16(y - __bfloat162float(hy));
    __nv_bfloat162 lp = __halves2bfloat162(lx, ly);
    lo = *reinterpret_cast<uint32_t*>(&lp);
}

// ---------------------------------------------------------------------------
// Split fp32 -> bf16 hi/lo pairs.  DST: 0=x, 1..4=Wq..Wo, 5=g_a
// ---------------------------------------------------------------------------
template <int DST>
__global__ void split_kernel(const float* __restrict__ src)
{
    const float* s = (DST == 5) ? (const float*)g_a : src;
    __nv_bfloat16* hi = (DST == 0) ? d_xh : (DST == 5) ? d_ah : d_wh[DST - 1];
    __nv_bfloat16* lo = (DST == 0) ? d_xl : (DST == 5) ? d_al : d_wl[DST - 1];

    int i4 = blockIdx.x * blockDim.x + threadIdx.x;
    float4 v = ((const float4*)s)[i4];
    __nv_bfloat16 h0 = __float2bfloat16(v.x);
    __nv_bfloat16 h1 = __float2bfloat16(v.y);
    __nv_bfloat16 h2 = __float2bfloat16(v.z);
    __nv_bfloat16 h3 = __float2bfloat16(v.w);
    __nv_bfloat16 l0 = __float2bfloat16(v.x - __bfloat162float(h0));
    __nv_bfloat16 l1 = __float2bfloat16(v.y - __bfloat162float(h1));
    __nv_bfloat16 l2 = __float2bfloat16(v.z - __bfloat162float(h2));
    __nv_bfloat16 l3 = __float2bfloat16(v.w - __bfloat162float(h3));
    ((__nv_bfloat162*)hi)[i4 * 2 + 0] = __halves2bfloat162(h0, h1);
    ((__nv_bfloat162*)hi)[i4 * 2 + 1] = __halves2bfloat162(h2, h3);
    ((__nv_bfloat162*)lo)[i4 * 2 + 0] = __halves2bfloat162(l0, l1);
    ((__nv_bfloat162*)lo)[i4 * 2 + 1] = __halves2bfloat162(l2, l3);
}

// ---------------------------------------------------------------------------
// mma.sync bf16-split GEMM (unchanged from R8, passing at 5e-5)
// ---------------------------------------------------------------------------
#define GEMM_SMEM (2 * 32768)

template <int WHICH>
__global__ __launch_bounds__(256) void gemm_mma(float* __restrict__ Cext)
{
    const __nv_bfloat16* Ah = (WHICH == 3) ? d_ah : d_xh;
    const __nv_bfloat16* Al = (WHICH == 3) ? d_al : d_xl;
    const __nv_bfloat16* Bh = d_wh[WHICH];
    const __nv_bfloat16* Bl = d_wl[WHICH];
    float* C = (WHICH == 0) ? g_q : (WHICH == 1) ? g_k
             : (WHICH == 2) ? g_v : Cext;

    extern __shared__ __align__(16) char smraw[];
    const uint32_t sb = s2u(smraw);

    const int tid  = threadIdx.x;
    const int lane = tid & 31;
    const int warp = tid >> 5;
    const int wm   = warp & 1;
    const int wn   = warp >> 1;
    const int bm   = blockIdx.y * 128;
    const int bn   = blockIdx.x * 128;

    float acc[16][4];
#pragma unroll
    for (int i = 0; i < 16; i++)
#pragma unroll
        for (int j = 0; j < 4; j++) acc[i][j] = 0.0f;

#define PREFETCH(kt, bi)                                                        \
    do {                                                                        \
        const int k0_ = (kt) * 32;                                              \
        const uint32_t bufb_ = sb + (bi) * 32768;                               \
        _Pragma("unroll")                                                       \
        for (int t_ = 0; t_ < 2; t_++) {                                        \
            int cid_ = tid + t_ * 256;                                          \
            int row_ = cid_ >> 2, ck_ = cid_ & 3;                               \
            uint32_t so_ = tile_off(row_, ck_);                                 \
            size_t ga_ = (size_t)(bm + row_) * DM + k0_ + ck_ * 8;              \
            size_t gb_ = (size_t)(bn + row_) * DM + k0_ + ck_ * 8;              \
            CPA16(bufb_ + so_,          Ah + ga_);                              \
            CPA16(bufb_ + 8192 + so_,   Al + ga_);                              \
            CPA16(bufb_ + 16384 + so_,  Bh + gb_);                              \
            CPA16(bufb_ + 24576 + so_,  Bl + gb_);                              \
        }                                                                       \
    } while (0)

    PREFETCH(0, 0);
    CPC();

    const int arow = (lane & 15) + wm * 64;
    const int acks = (lane >> 4);
    const int bnrw = wn * 32 + (lane & 7) + ((lane >> 4) << 3);
    const int bcks = ((lane >> 3) & 1);

    for (int kt = 0; kt < 128; kt++) {
        const int bi = kt & 1;
        if (kt + 1 < 128) {
            PREFETCH(kt + 1, (kt + 1) & 1);
            CPC();
            CPW1();
        } else {
            CPW0();
        }
        __syncthreads();

        const uint32_t bAh = sb + bi * 32768;
        const uint32_t bAl = bAh + 8192;
        const uint32_t bBh = bAh + 16384;
        const uint32_t bBl = bAh + 24576;

#pragma unroll
        for (int s = 0; s < 2; s++) {
            uint32_t ah[4][4], al[4][4], bh[4][2], bl[4][2];
            const int ack = 2 * s + acks;
            const int bck = 2 * s + bcks;
#pragma unroll
            for (int mt = 0; mt < 4; mt++) {
                uint32_t off = tile_off(arow + mt * 16, ack);
                LDSM4(ah[mt][0], ah[mt][1], ah[mt][2], ah[mt][3], bAh + off);
                LDSM4(al[mt][0], al[mt][1], al[mt][2], al[mt][3], bAl + off);
            }
#pragma unroll
            for (int p = 0; p < 2; p++) {
                uint32_t off = tile_off(bnrw + p * 16, bck);
                uint32_t t0, t1, t2, t3;
                LDSM4(t0, t1, t2, t3, bBh + off);
                bh[2 * p][0] = t0; bh[2 * p][1] = t1;
                bh[2 * p + 1][0] = t2; bh[2 * p + 1][1] = t3;
                LDSM4(t0, t1, t2, t3, bBl + off);
                bl[2 * p][0] = t0; bl[2 * p][1] = t1;
                bl[2 * p + 1][0] = t2; bl[2 * p + 1][1] = t3;
            }
#pragma unroll
            for (int mt = 0; mt < 4; mt++)
#pragma unroll
                for (int nt = 0; nt < 4; nt++) {
                    mma16816(acc[mt * 4 + nt], ah[mt], bh[nt]);
                    mma16816(acc[mt * 4 + nt], ah[mt], bl[nt]);
                    mma16816(acc[mt * 4 + nt], al[mt], bh[nt]);
                }
        }
        __syncthreads();
    }

#pragma unroll
    for (int mt = 0; mt < 4; mt++)
#pragma unroll
        for (int nt = 0; nt < 4; nt++) {
            int row = bm + wm * 64 + mt * 16 + (lane >> 2);
            int col = bn + wn * 32 + nt * 8 + 2 * (lane & 3);
            float* c0 = C + (size_t)row * DM + col;
            float* c1 = C + (size_t)(row + 8) * DM + col;
            float2 v0 = { acc[mt * 4 + nt][0], acc[mt * 4 + nt][1] };
            float2 v1 = { acc[mt * 4 + nt][2], acc[mt * 4 + nt][3] };
            *(float2*)c0 = v0;
            *(float2*)c1 = v1;
        }
#undef PREFETCH
}

// ---------------------------------------------------------------------------
// RoPE + bf16 hi/lo split: g_q (pre-scaled by 1/sqrt(HD)) -> d_qh/d_ql,
// g_k -> d_kh2/d_kl2.
// ---------------------------------------------------------------------------
__global__ void rope_split_kernel()
{
    int idx = blockIdx.x * blockDim.x + threadIdx.x;
    int d = idx & 63;
    int s = idx >> 11;
    const float LOG2_10000 = 13.287712379549449f;
    const float SCALE = 0.08838834764831845f;
    float ex   = (float)(2 * d) * (1.0f / 128.0f);
    float invf = exp2f(-ex * LOG2_10000);
    float ang  = (float)s * invf;
    float cv = cosf(ang), sv = sinf(ang);
    int h = (idx >> 6) & 31;
    size_t base = (size_t)s * DM + h * HD + d;

    float q1 = g_q[base], q2 = g_q[base + 64];
    float qa = (q1 * cv - q2 * sv) * SCALE;
    float qb = (q2 * cv + q1 * sv) * SCALE;
    __nv_bfloat16 ha = __float2bfloat16(qa);
    __nv_bfloat16 hb = __float2bfloat16(qb);
    d_qh[base]      = ha; d_ql[base]      = __float2bfloat16(qa - __bfloat162float(ha));
    d_qh[base + 64] = hb; d_ql[base + 64] = __float2bfloat16(qb - __bfloat162float(hb));

    float k1 = g_k[base], k2 = g_k[base + 64];
    float ka = k1 * cv - k2 * sv;
    float kb = k2 * cv + k1 * sv;
    __nv_bfloat16 hc = __float2bfloat16(ka);
    __nv_bfloat16 hd_ = __float2bfloat16(kb);
    d_kh2[base]      = hc;  d_kl2[base]      = __float2bfloat16(ka - __bfloat162float(hc));
    d_kh2[base + 64] = hd_; d_kl2[base + 64] = __float2bfloat16(kb - __bfloat162float(hd_));
}

// ---------------------------------------------------------------------------
// V transpose + split: g_v[s][c] -> d_vth/d_vtl[c][s]  (c = h*128+d)
// ---------------------------------------------------------------------------
__global__ void vsplit_t_kernel()
{
    __shared__ float ts[32][33];
    const int bs = blockIdx.x * 32;           // s tile
    const int bc = blockIdx.y * 32;           // c tile
    const int tx = threadIdx.x & 31;
    const int ty = threadIdx.x >> 5;          // 0..7
#pragma unroll
    for (int i = 0; i < 4; i++) {
        int row = ty + i * 8;
        ts[row][tx] = g_v[(size_t)(bs + row) * DM + bc + tx];
    }
    __syncthreads();
#pragma unroll
    for (int i = 0; i < 4; i++) {
        int row = ty + i * 8;                 // c offset
        float v = ts[tx][row];
        __nv_bfloat16 hi = __float2bfloat16(v);
        size_t o = (size_t)(bc + row) * S_LEN + bs + tx;
        d_vth[o] = hi;
        d_vtl[o] = __float2bfloat16(v - __bfloat162float(hi));
    }
}

// ---------------------------------------------------------------------------
// Flash attention via mma.sync bf16-split.  BM=128, BN=64 keys/iter, D=128.
// 8 warps, warp owns 16 q-rows.  Smem: Qh/Ql resident (64 KB) + 2x64 KB KV.
// ---------------------------------------------------------------------------
#define ATTN_SMEM (65536 + 2 * 65536)   // 192 KB

__global__ __launch_bounds__(256, 1) void attn_mma()
{
    extern __shared__ __align__(16) char araw[];
    const uint32_t sb  = s2u(araw);
    const uint32_t sQh = sb, sQl = sb + 32768;

    const int qtb = blockIdx.x;
    const int h   = blockIdx.y;
    const int q0  = qtb * 128;
    const int tid = threadIdx.x;
    const int lane = tid & 31;
    const int warp = tid >> 5;
    const int R   = warp * 16;

    // Q tiles (async, group 0 with first KV tile)
#pragma unroll
    for (int t = 0; t < 8; t++) {
        int cid = tid + t * 256;
        int r = cid >> 4, c = cid & 15;
        size_t g = (size_t)(q0 + r) * DM + h * HD + c * 8;
        uint32_t so = r * 256 + swz16(r, c) * 16;
        CPA16(sQh + so, d_qh + g);
        CPA16(sQl + so, d_ql + g);
    }

#define PRE_KV(k0_, bi_)                                                        \
    do {                                                                        \
        const uint32_t bb_ = sb + 65536 + (bi_) * 65536;                        \
        _Pragma("unroll")                                                       \
        for (int t_ = 0; t_ < 4; t_++) {                                        \
            int cid_ = tid + t_ * 256;                                          \
            int kr_ = cid_ >> 4, kc_ = cid_ & 15;                               \
            size_t gk_ = (size_t)((k0_) + kr_) * DM + h * HD + kc_ * 8;         \
            uint32_t ko_ = kr_ * 256 + swz16(kr_, kc_) * 16;                    \
            CPA16(bb_ + ko_,         d_kh2 + gk_);                              \
            CPA16(bb_ + 16384 + ko_, d_kl2 + gk_);                              \
            int vr_ = cid_ >> 3, vc_ = cid_ & 7;                                \
            size_t gv_ = (size_t)(h * HD + vr_) * S_LEN + (k0_) + vc_ * 8;      \
            uint32_t vo_ = vr_ * 128 + swz8(vr_, vc_) * 16;                     \
            CPA16(bb_ + 32768 + vo_, d_vth + gv_);                              \
            CPA16(bb_ + 49152 + vo_, d_vtl + gv_);                              \
        }                                                                       \
    } while (0)

    int kb_lo = 2 * qtb - 16; if (kb_lo < 0) kb_lo = 0;
    const int niter = 2 * qtb + 1 - kb_lo + 1;

    PRE_KV(kb_lo * 64, 0);
    CPC();

    float m0 = -1e30f, m1 = -1e30f, l0 = 0.0f, l1 = 0.0f;
    float o[16][4];
#pragma unroll
    for (int p = 0; p < 16; p++)
#pragma unroll
        for (int j = 0; j < 4; j++) o[p][j] = 0.0f;

    const int r0  = lane >> 2;
    const int cb  = 2 * (lane & 3);
    const int gi0 = q0 + R + r0;
    const int gi1 = gi0 + 8;

    for (int it = 0; it < niter; it++) {
        const int k0 = (kb_lo + it) * 64;
        const int bi = it & 1;
        if (it + 1 < niter) {
            PRE_KV(k0 + 64, (it + 1) & 1);
            CPC();
            CPW1();
        } else {
            CPW0();
        }
        __syncthreads();

        const uint32_t bKh = sb + 65536 + bi * 65536;
        const uint32_t bKl = bKh + 16384;
        const uint32_t bVh = bKh + 32768;
        const uint32_t bVl = bKh + 49152;

        // ---- S = Q K^T (3-way split)
        float s[8][4];
#pragma unroll
        for (int j = 0; j < 8; j++)
#pragma unroll
            for (int e = 0; e < 4; e++) s[j][e] = 0.0f;

#pragma unroll
        for (int ks = 0; ks < 8; ks++) {
            const int qrow = R + (lane & 15);
            const int qc   = 2 * ks + (lane >> 4);
            uint32_t qoff  = qrow * 256 + swz16(qrow, qc) * 16;
            uint32_t qh4[4], ql4[4];
            LDSM4(qh4[0], qh4[1], qh4[2], qh4[3], sQh + qoff);
            LDSM4(ql4[0], ql4[1], ql4[2], ql4[3], sQl + qoff);
            const int bck = 2 * ks + ((lane >> 3) & 1);
#pragma unroll
            for (int p = 0; p < 4; p++) {
                const int krow = p * 16 + (lane & 7) + ((lane >> 4) << 3);
                uint32_t koff = krow * 256 + swz16(krow, bck) * 16;
                uint32_t kh4[4], kl4[4];
                LDSM4(kh4[0], kh4[1], kh4[2], kh4[3], bKh + koff);
                LDSM4(kl4[0], kl4[1], kl4[2], kl4[3], bKl + koff);
                mma16816(s[2 * p],     qh4, kh4 + 0);
                mma16816(s[2 * p + 1], qh4, kh4 + 2);
                mma16816(s[2 * p],     qh4, kl4 + 0);
                mma16816(s[2 * p + 1], qh4, kl4 + 2);
                mma16816(s[2 * p],     ql4, kh4 + 0);
                mma16816(s[2 * p + 1], ql4, kh4 + 2);
            }
        }

        // ---- mask (skip for interior tiles)
        const bool need_mask = !((k0 + 63 <= q0 + R) && (k0 >= q0 + R - 1008));
        if (need_mask) {
#pragma unroll
            for (int j = 0; j < 8; j++) {
                int gj0 = k0 + j * 8 + cb, gj1 = gj0 + 1;
                if (gj0 > gi0 || gj0 + WIN <= gi0) s[j][0] = -1e30f;
                if (gj1 > gi0 || gj1 + WIN <= gi0) s[j][1] = -1e30f;
                if (gj0 > gi1 || gj0 + WIN <= gi1) s[j][2] = -1e30f;
                if (gj1 > gi1 || gj1 + WIN <= gi1) s[j][3] = -1e30f;
            }
        }

        // ---- online softmax (quad reductions)
        float t0 = -1e30f, t1 = -1e30f;
#pragma unroll
        for (int j = 0; j < 8; j++) {
            t0 = fmaxf(t0, fmaxf(s[j][0], s[j][1]));
            t1 = fmaxf(t1, fmaxf(s[j][2], s[j][3]));
        }
        t0 = fmaxf(t0, __shfl_xor_sync(0xffffffffu, t0, 1));
        t0 = fmaxf(t0, __shfl_xor_sync(0xffffffffu, t0, 2));
        t1 = fmaxf(t1, __shfl_xor_sync(0xffffffffu, t1, 1));
        t1 = fmaxf(t1, __shfl_xor_sync(0xffffffffu, t1, 2));
        float mn0 = fmaxf(m0, t0), mn1 = fmaxf(m1, t1);
        float c0 = __expf(m0 - mn0), c1 = __expf(m1 - mn1);
        m0 = mn0; m1 = mn1;
        float rs0 = 0.0f, rs1 = 0.0f;
#pragma unroll
        for (int j = 0; j < 8; j++) {
            s[j][0] = __expf(s[j][0] - mn0); rs0 += s[j][0];
            s[j][1] = __expf(s[j][1] - mn0); rs0 += s[j][1];
            s[j][2] = __expf(s[j][2] - mn1); rs1 += s[j][2];
            s[j][3] = __expf(s[j][3] - mn1); rs1 += s[j][3];
        }
        rs0 += __shfl_xor_sync(0xffffffffu, rs0, 1);
        rs0 += __shfl_xor_sync(0xffffffffu, rs0, 2);
        rs1 += __shfl_xor_sync(0xffffffffu, rs1, 1);
        rs1 += __shfl_xor_sync(0xffffffffu, rs1, 2);
        l0 = l0 * c0 + rs0;
        l1 = l1 * c1 + rs1;
#pragma unroll
        for (int p = 0; p < 16; p++) {
            o[p][0] *= c0; o[p][1] *= c0;
            o[p][2] *= c1; o[p][3] *= c1;
        }

        // ---- P -> A fragments (C layout == A layout), hi/lo split
        uint32_t pah[4][4], pal[4][4];
#pragma unroll
        for (int ks2 = 0; ks2 < 4; ks2++) {
            int j = 2 * ks2;
            split2(s[j][0],     s[j][1],     pah[ks2][0], pal[ks2][0]);
            split2(s[j][2],     s[j][3],     pah[ks2][1], pal[ks2][1]);
            split2(s[j + 1][0], s[j + 1][1], pah[ks2][2], pal[ks2][2]);
            split2(s[j + 1][2], s[j + 1][3], pah[ks2][3], pal[ks2][3]);
        }

        // ---- O += P V  (V^T tiles, B pattern identical to GEMM)
#pragma unroll
        for (int ks2 = 0; ks2 < 4; ks2++) {
            const int vck = 2 * ks2 + ((lane >> 3) & 1);
#pragma unroll
            for (int p = 0; p < 8; p++) {
                const int vrow = p * 16 + (lane & 7) + ((lane >> 4) << 3);
                uint32_t voff = vrow * 128 + swz8(vrow, vck) * 16;
                uint32_t vh4[4], vl4[4];
                LDSM4(vh4[0], vh4[1], vh4[2], vh4[3], bVh + voff);
                LDSM4(vl4[0], vl4[1], vl4[2], vl4[3], bVl + voff);
                mma16816(o[2 * p],     pah[ks2], vh4 + 0);
                mma16816(o[2 * p + 1], pah[ks2], vh4 + 2);
                mma16816(o[2 * p],     pah[ks2], vl4 + 0);
                mma16816(o[2 * p + 1], pah[ks2], vl4 + 2);
                mma16816(o[2 * p],     pal[ks2], vh4 + 0);
                mma16816(o[2 * p + 1], pal[ks2], vh4 + 2);
            }
        }
        __syncthreads();
    }

    // ---- epilogue
    const float inv0 = 1.0f / l0;
    const float inv1 = 1.0f / l1;
#pragma unroll
    for (int p = 0; p < 16; p++) {
        int col = h * HD + p * 8 + cb;
        float2 v0 = { o[p][0] * inv0, o[p][1] * inv0 };
        float2 v1 = { o[p][2] * inv1, o[p][3] * inv1 };
        *(float2*)(g_a + (size_t)gi0 * DM + col) = v0;
        *(float2*)(g_a + (size_t)gi1 * DM + col) = v1;
    }
#undef PRE_KV
}

// ---------------------------------------------------------------------------
extern "C" void kernel_launch(void* const* d_in, const int* in_sizes, int n_in,
                              void* d_out, int out_size)
{
    (void)in_sizes; (void)n_in; (void)out_size;
    const float* x  = (const float*)d_in[0];
    const float* Wq = (const float*)d_in[1];
    const float* Wk = (const float*)d_in[2];
    const float* Wv = (const float*)d_in[3];
    const float* Wo = (const float*)d_in[4];
    float* out = (float*)d_out;

    cudaFuncSetAttribute(gemm_mma<0>, cudaFuncAttributeMaxDynamicSharedMemorySize, GEMM_SMEM);
    cudaFuncSetAttribute(gemm_mma<1>, cudaFuncAttributeMaxDynamicSharedMemorySize, GEMM_SMEM);
    cudaFuncSetAttribute(gemm_mma<2>, cudaFuncAttributeMaxDynamicSharedMemorySize, GEMM_SMEM);
    cudaFuncSetAttribute(gemm_mma<3>, cudaFuncAttributeMaxDynamicSharedMemorySize, GEMM_SMEM);
    cudaFuncSetAttribute(attn_mma,    cudaFuncAttributeMaxDynamicSharedMemorySize, ATTN_SMEM);

    const int XB = (S_LEN * DM) / 1024;
    const int WB = (DM * DM) / 1024;

    split_kernel<0><<<XB, 256>>>(x);
    split_kernel<1><<<WB, 256>>>(Wq);
    split_kernel<2><<<WB, 256>>>(Wk);
    split_kernel<3><<<WB, 256>>>(Wv);
    split_kernel<4><<<WB, 256>>>(Wo);

    dim3 gg(DM / 128, S_LEN / 128);
    gemm_mma<0><<<gg, 256, GEMM_SMEM>>>(nullptr);
    gemm_mma<1><<<gg, 256, GEMM_SMEM>>>(nullptr);
    gemm_mma<2><<<gg, 256, GEMM_SMEM>>>(nullptr);

    rope_split_kernel<<<(S_LEN * NH * 64) / 256, 256>>>();
    vsplit_t_kernel<<<dim3(S_LEN / 32, DM / 32), 256>>>();

    attn_mma<<<dim3(S_LEN / 128, NH), 256, ATTN_SMEM>>>();

    split_kernel<5><<<XB, 256>>>(nullptr);
    gemm_mma<3><<<gg, 256, GEMM_SMEM>>>(out);
}

// round 10
// speedup vs baseline: 3.3757x; 1.1478x over previous
#include <cuda_runtime.h>
#include <cuda_bf16.h>
#include <cstdint>

#define S_LEN 2048
#define DM    4096
#define NH    32
#define HD    128
#define WIN   1024

// ---------------- scratch (__device__ globals; no allocation APIs) ----------
__device__ float g_q[S_LEN * DM];
__device__ float g_k[S_LEN * DM];
__device__ float g_v[S_LEN * DM];
__device__ float g_a[S_LEN * DM];

__device__ __nv_bfloat16 d_xh[S_LEN * DM], d_xl[S_LEN * DM];   // x split
__device__ __nv_bfloat16 d_ah[S_LEN * DM], d_al[S_LEN * DM];   // attn-out split
__device__ __nv_bfloat16 d_wh[4][DM * DM], d_wl[4][DM * DM];   // Wq,Wk,Wv,Wo

// attention operands (bf16 hi/lo)
__device__ __nv_bfloat16 d_qh[S_LEN * DM], d_ql[S_LEN * DM];   // Q (pre-scaled)
__device__ __nv_bfloat16 d_kh2[S_LEN * DM], d_kl2[S_LEN * DM]; // K
__device__ __nv_bfloat16 d_vth[S_LEN * DM], d_vtl[S_LEN * DM]; // V^T [h*128+d][s]

// ---------------- PTX helpers (sm_80-class only) ----------------------------
__device__ __forceinline__ uint32_t s2u(const void* p) {
    uint32_t r;
    asm("{ .reg .u64 t; cvta.to.shared.u64 t, %1; cvt.u32.u64 %0, t; }"
        : "=r"(r) : "l"(p));
    return r;
}
#define LDSM4(r0, r1, r2, r3, addr) \
    asm volatile("ldmatrix.sync.aligned.m8n8.x4.shared.b16 {%0,%1,%2,%3}, [%4];" \
        : "=r"(r0), "=r"(r1), "=r"(r2), "=r"(r3) : "r"(addr))
__device__ __forceinline__ void mma16816(float* c, const uint32_t* a, const uint32_t* b) {
    asm volatile(
        "mma.sync.aligned.m16n8k16.row.col.f32.bf16.bf16.f32 "
        "{%0,%1,%2,%3}, {%4,%5,%6,%7}, {%8,%9}, {%0,%1,%2,%3};"
        : "+f"(c[0]), "+f"(c[1]), "+f"(c[2]), "+f"(c[3])
        : "r"(a[0]), "r"(a[1]), "r"(a[2]), "r"(a[3]), "r"(b[0]), "r"(b[1]));
}
#define CPA16(dst, src) \
    asm volatile("cp.async.cg.shared.global [%0], [%1], 16;" :: "r"(dst), "l"(src))
#define CPC() asm volatile("cp.async.commit_group;")
#define CPW1() asm volatile("cp.async.wait_group 1;")
#define CPW0() asm volatile("cp.async.wait_group 0;")

// 16B-chunk XOR swizzles
__device__ __forceinline__ uint32_t tile_off(int row, int ck) {        // 4 chunks/row
    return (uint32_t)(((row << 2) + (ck ^ ((row >> 1) & 3))) << 4);
}
__device__ __forceinline__ uint32_t swz16(int r, int c) {              // 16 chunks/row
    return (uint32_t)((c & 8) | ((c ^ (r & 7)) & 7));
}
__device__ __forceinline__ uint32_t swz8(int r, int c) {               // 8 chunks/row
    return (uint32_t)(c ^ (r & 7));
}
__device__ __forceinline__ void split2(float x, float y, uint32_t& hi, uint32_t& lo) {
    __nv_bfloat16 hx = __float2bfloat16(x), hy = __float2bfloat16(y);
    __nv_bfloat162 hp = __halves2bfloat162(hx, hy);
    hi = *reinterpret_cast<uint32_t*>(&hp);
    __nv_bfloat16 lx = __float2bfloat16(x - __bfloat162float(hx));
    __nv_bfloat16 ly = __float2bfloat16(y - __bfloat162float(hy));
    __nv_bfloat162 lp = __halves2bfloat162(lx, ly);
    lo = *reinterpret_cast<uint32_t*>(&lp);
}

// ---------------------------------------------------------------------------
// Split fp32 -> bf16 hi/lo
// ---------------------------------------------------------------------------
__device__ __forceinline__ void split_body(const float* __restrict__ s,
                                           __nv_bfloat16* __restrict__ hi,
                                           __nv_bfloat16* __restrict__ lo, int i4)
{
    float4 v = ((const float4*)s)[i4];
    __nv_bfloat16 h0 = __float2bfloat16(v.x);
    __nv_bfloat16 h1 = __float2bfloat16(v.y);
    __nv_bfloat16 h2 = __float2bfloat16(v.z);
    __nv_bfloat16 h3 = __float2bfloat16(v.w);
    __nv_bfloat16 l0 = __float2bfloat16(v.x - __bfloat162float(h0));
    __nv_bfloat16 l1 = __float2bfloat16(v.y - __bfloat162float(h1));
    __nv_bfloat16 l2 = __float2bfloat16(v.z - __bfloat162float(h2));
    __nv_bfloat16 l3 = __float2bfloat16(v.w - __bfloat162float(h3));
    ((__nv_bfloat162*)hi)[i4 * 2 + 0] = __halves2bfloat162(h0, h1);
    ((__nv_bfloat162*)hi)[i4 * 2 + 1] = __halves2bfloat162(h2, h3);
    ((__nv_bfloat162*)lo)[i4 * 2 + 0] = __halves2bfloat162(l0, l1);
    ((__nv_bfloat162*)lo)[i4 * 2 + 1] = __halves2bfloat162(l2, l3);
}

__global__ void split_x_kernel(const float* __restrict__ src)   // x -> d_xh/d_xl
{
    int i4 = blockIdx.x * blockDim.x + threadIdx.x;
    split_body(src, d_xh, d_xl, i4);
}
__global__ void split_a_kernel()                                // g_a -> d_ah/d_al
{
    int i4 = blockIdx.x * blockDim.x + threadIdx.x;
    split_body(g_a, d_ah, d_al, i4);
}
// all four weights in one launch: grid = 4 * 16384
__global__ void split_w_kernel(const float* __restrict__ Wq, const float* __restrict__ Wk,
                               const float* __restrict__ Wv, const float* __restrict__ Wo)
{
    int w  = blockIdx.x >> 14;
    int i4 = (blockIdx.x & 16383) * blockDim.x + threadIdx.x;
    const float* s = (w == 0) ? Wq : (w == 1) ? Wk : (w == 2) ? Wv : Wo;
    split_body(s, d_wh[w], d_wl[w], i4);
}

// ---------------------------------------------------------------------------
// mma.sync bf16-split GEMM body (identical math to R8/R9, 5e-5-proven)
// BM=BN=128, BK=32, 256 thr, cp.async 2-stage.
// ---------------------------------------------------------------------------
#define GEMM_SMEM (2 * 32768)

__device__ __forceinline__ void gemm_body(
    const __nv_bfloat16* __restrict__ Ah, const __nv_bfloat16* __restrict__ Al,
    const __nv_bfloat16* __restrict__ Bh, const __nv_bfloat16* __restrict__ Bl,
    float* __restrict__ C, int bm, int bn, uint32_t sb)
{
    const int tid  = threadIdx.x;
    const int lane = tid & 31;
    const int warp = tid >> 5;
    const int wm   = warp & 1;
    const int wn   = warp >> 1;

    float acc[16][4];
#pragma unroll
    for (int i = 0; i < 16; i++)
#pragma unroll
        for (int j = 0; j < 4; j++) acc[i][j] = 0.0f;

#define PREFETCH(kt, bi)                                                        \
    do {                                                                        \
        const int k0_ = (kt) * 32;                                              \
        const uint32_t bufb_ = sb + (bi) * 32768;                               \
        _Pragma("unroll")                                                       \
        for (int t_ = 0; t_ < 2; t_++) {                                        \
            int cid_ = tid + t_ * 256;                                          \
            int row_ = cid_ >> 2, ck_ = cid_ & 3;                               \
            uint32_t so_ = tile_off(row_, ck_);                                 \
            size_t ga_ = (size_t)(bm + row_) * DM + k0_ + ck_ * 8;              \
            size_t gb_ = (size_t)(bn + row_) * DM + k0_ + ck_ * 8;              \
            CPA16(bufb_ + so_,          Ah + ga_);                              \
            CPA16(bufb_ + 8192 + so_,   Al + ga_);                              \
            CPA16(bufb_ + 16384 + so_,  Bh + gb_);                              \
            CPA16(bufb_ + 24576 + so_,  Bl + gb_);                              \
        }                                                                       \
    } while (0)

    PREFETCH(0, 0);
    CPC();

    const int arow = (lane & 15) + wm * 64;
    const int acks = (lane >> 4);
    const int bnrw = wn * 32 + (lane & 7) + ((lane >> 4) << 3);
    const int bcks = ((lane >> 3) & 1);

    for (int kt = 0; kt < 128; kt++) {
        const int bi = kt & 1;
        if (kt + 1 < 128) {
            PREFETCH(kt + 1, (kt + 1) & 1);
            CPC();
            CPW1();
        } else {
            CPW0();
        }
        __syncthreads();

        const uint32_t bAh = sb + bi * 32768;
        const uint32_t bAl = bAh + 8192;
        const uint32_t bBh = bAh + 16384;
        const uint32_t bBl = bAh + 24576;

#pragma unroll
        for (int s = 0; s < 2; s++) {
            uint32_t ah[4][4], al[4][4], bh[4][2], bl[4][2];
            const int ack = 2 * s + acks;
            const int bck = 2 * s + bcks;
#pragma unroll
            for (int mt = 0; mt < 4; mt++) {
                uint32_t off = tile_off(arow + mt * 16, ack);
                LDSM4(ah[mt][0], ah[mt][1], ah[mt][2], ah[mt][3], bAh + off);
                LDSM4(al[mt][0], al[mt][1], al[mt][2], al[mt][3], bAl + off);
            }
#pragma unroll
            for (int p = 0; p < 2; p++) {
                uint32_t off = tile_off(bnrw + p * 16, bck);
                uint32_t t0, t1, t2, t3;
                LDSM4(t0, t1, t2, t3, bBh + off);
                bh[2 * p][0] = t0; bh[2 * p][1] = t1;
                bh[2 * p + 1][0] = t2; bh[2 * p + 1][1] = t3;
                LDSM4(t0, t1, t2, t3, bBl + off);
                bl[2 * p][0] = t0; bl[2 * p][1] = t1;
                bl[2 * p + 1][0] = t2; bl[2 * p + 1][1] = t3;
            }
#pragma unroll
            for (int mt = 0; mt < 4; mt++)
#pragma unroll
                for (int nt = 0; nt < 4; nt++) {
                    mma16816(acc[mt * 4 + nt], ah[mt], bh[nt]);
                    mma16816(acc[mt * 4 + nt], ah[mt], bl[nt]);
                    mma16816(acc[mt * 4 + nt], al[mt], bh[nt]);
                }
        }
        __syncthreads();
    }

#pragma unroll
    for (int mt = 0; mt < 4; mt++)
#pragma unroll
        for (int nt = 0; nt < 4; nt++) {
            int row = bm + wm * 64 + mt * 16 + (lane >> 2);
            int col = bn + wn * 32 + nt * 8 + 2 * (lane & 3);
            float* c0 = C + (size_t)row * DM + col;
            float* c1 = C + (size_t)(row + 8) * DM + col;
            float2 v0 = { acc[mt * 4 + nt][0], acc[mt * 4 + nt][1] };
            float2 v1 = { acc[mt * 4 + nt][2], acc[mt * 4 + nt][3] };
            *(float2*)c0 = v0;
            *(float2*)c1 = v1;
        }
#undef PREFETCH
}

// fused Q/K/V projection: grid (96, 16); x-block picks weight + n-tile
__global__ __launch_bounds__(256) void gemm_qkv()
{
    extern __shared__ __align__(16) char smraw[];
    const int which = blockIdx.x >> 5;            // 0,1,2
    const int bn    = (blockIdx.x & 31) * 128;
    const int bm    = blockIdx.y * 128;
    float* C = (which == 0) ? g_q : (which == 1) ? g_k : g_v;
    gemm_body(d_xh, d_xl, d_wh[which], d_wl[which], C, bm, bn, s2u(smraw));
}

// output projection
__global__ __launch_bounds__(256) void gemm_wo(float* __restrict__ out)
{
    extern __shared__ __align__(16) char smraw[];
    gemm_body(d_ah, d_al, d_wh[3], d_wl[3], out,
              blockIdx.y * 128, blockIdx.x * 128, s2u(smraw));
}

// ---------------------------------------------------------------------------
// RoPE + bf16 split (Q pre-scaled)
// ---------------------------------------------------------------------------
__global__ void rope_split_kernel()
{
    int idx = blockIdx.x * blockDim.x + threadIdx.x;
    int d = idx & 63;
    int s = idx >> 11;
    const float LOG2_10000 = 13.287712379549449f;
    const float SCALE = 0.08838834764831845f;
    float ex   = (float)(2 * d) * (1.0f / 128.0f);
    float invf = exp2f(-ex * LOG2_10000);
    float ang  = (float)s * invf;
    float cv = cosf(ang), sv = sinf(ang);
    int h = (idx >> 6) & 31;
    size_t base = (size_t)s * DM + h * HD + d;

    float q1 = g_q[base], q2 = g_q[base + 64];
    float qa = (q1 * cv - q2 * sv) * SCALE;
    float qb = (q2 * cv + q1 * sv) * SCALE;
    __nv_bfloat16 ha = __float2bfloat16(qa);
    __nv_bfloat16 hb = __float2bfloat16(qb);
    d_qh[base]      = ha; d_ql[base]      = __float2bfloat16(qa - __bfloat162float(ha));
    d_qh[base + 64] = hb; d_ql[base + 64] = __float2bfloat16(qb - __bfloat162float(hb));

    float k1 = g_k[base], k2 = g_k[base + 64];
    float ka = k1 * cv - k2 * sv;
    float kb = k2 * cv + k1 * sv;
    __nv_bfloat16 hc = __float2bfloat16(ka);
    __nv_bfloat16 hd_ = __float2bfloat16(kb);
    d_kh2[base]      = hc;  d_kl2[base]      = __float2bfloat16(ka - __bfloat162float(hc));
    d_kh2[base + 64] = hd_; d_kl2[base + 64] = __float2bfloat16(kb - __bfloat162float(hd_));
}

// ---------------------------------------------------------------------------
// V transpose + split
// ---------------------------------------------------------------------------
__global__ void vsplit_t_kernel()
{
    __shared__ float ts[32][33];
    const int bs = blockIdx.x * 32;
    const int bc = blockIdx.y * 32;
    const int tx = threadIdx.x & 31;
    const int ty = threadIdx.x >> 5;
#pragma unroll
    for (int i = 0; i < 4; i++) {
        int row = ty + i * 8;
        ts[row][tx] = g_v[(size_t)(bs + row) * DM + bc + tx];
    }
    __syncthreads();
#pragma unroll
    for (int i = 0; i < 4; i++) {
        int row = ty + i * 8;
        float v = ts[tx][row];
        __nv_bfloat16 hi = __float2bfloat16(v);
        size_t o = (size_t)(bc + row) * S_LEN + bs + tx;
        d_vth[o] = hi;
        d_vtl[o] = __float2bfloat16(v - __bfloat162float(hi));
    }
}

// ---------------------------------------------------------------------------
// Flash attention (batched-LDSM restructure of R9).  BM=128, BN=64, D=128.
// ---------------------------------------------------------------------------
#define ATTN_SMEM (65536 + 2 * 65536)   // 192 KB

__global__ __launch_bounds__(256, 1) void attn_mma()
{
    extern __shared__ __align__(16) char araw[];
    const uint32_t sb  = s2u(araw);
    const uint32_t sQh = sb, sQl = sb + 32768;

    // reversed order: long (diagonal) q-tiles scheduled first
    const int qtb = (int)(gridDim.x - 1) - (int)blockIdx.x;
    const int h   = blockIdx.y;
    const int q0  = qtb * 128;
    const int tid = threadIdx.x;
    const int lane = tid & 31;
    const int warp = tid >> 5;
    const int R   = warp * 16;

#pragma unroll
    for (int t = 0; t < 8; t++) {
        int cid = tid + t * 256;
        int r = cid >> 4, c = cid & 15;
        size_t g = (size_t)(q0 + r) * DM + h * HD + c * 8;
        uint32_t so = r * 256 + swz16(r, c) * 16;
        CPA16(sQh + so, d_qh + g);
        CPA16(sQl + so, d_ql + g);
    }

#define PRE_KV(k0_, bi_)                                                        \
    do {                                                                        \
        const uint32_t bb_ = sb + 65536 + (bi_) * 65536;                        \
        _Pragma("unroll")                                                       \
        for (int t_ = 0; t_ < 4; t_++) {                                        \
            int cid_ = tid + t_ * 256;                                          \
            int kr_ = cid_ >> 4, kc_ = cid_ & 15;                               \
            size_t gk_ = (size_t)((k0_) + kr_) * DM + h * HD + kc_ * 8;         \
            uint32_t ko_ = kr_ * 256 + swz16(kr_, kc_) * 16;                    \
            CPA16(bb_ + ko_,         d_kh2 + gk_);                              \
            CPA16(bb_ + 16384 + ko_, d_kl2 + gk_);                              \
            int vr_ = cid_ >> 3, vc_ = cid_ & 7;                                \
            size_t gv_ = (size_t)(h * HD + vr_) * S_LEN + (k0_) + vc_ * 8;      \
            uint32_t vo_ = vr_ * 128 + swz8(vr_, vc_) * 16;                     \
            CPA16(bb_ + 32768 + vo_, d_vth + gv_);                              \
            CPA16(bb_ + 49152 + vo_, d_vtl + gv_);                              \
        }                                                                       \
    } while (0)

    int kb_lo = 2 * qtb - 16; if (kb_lo < 0) kb_lo = 0;
    const int niter = 2 * qtb + 1 - kb_lo + 1;

    PRE_KV(kb_lo * 64, 0);
    CPC();

    float m0 = -1e30f, m1 = -1e30f, l0 = 0.0f, l1 = 0.0f;
    float o[16][4];
#pragma unroll
    for (int p = 0; p < 16; p++)
#pragma unroll
        for (int j = 0; j < 4; j++) o[p][j] = 0.0f;

    const int r0  = lane >> 2;
    const int cb  = 2 * (lane & 3);
    const int gi0 = q0 + R + r0;
    const int gi1 = gi0 + 8;

    for (int it = 0; it < niter; it++) {
        const int k0 = (kb_lo + it) * 64;
        const int bi = it & 1;
        if (it + 1 < niter) {
            PRE_KV(k0 + 64, (it + 1) & 1);
            CPC();
            CPW1();
        } else {
            CPW0();
        }
        __syncthreads();

        const uint32_t bKh = sb + 65536 + bi * 65536;
        const uint32_t bKl = bKh + 16384;
        const uint32_t bVh = bKh + 32768;
        const uint32_t bVl = bKh + 49152;

        // ---- S = Q K^T: batch all LDSMs per ks, then 24-MMA block
        float s[8][4];
#pragma unroll
        for (int j = 0; j < 8; j++)
#pragma unroll
            for (int e = 0; e < 4; e++) s[j][e] = 0.0f;

#pragma unroll
        for (int ks = 0; ks < 8; ks++) {
            const int qrow = R + (lane & 15);
            const int qc   = 2 * ks + (lane >> 4);
            uint32_t qoff  = qrow * 256 + swz16(qrow, qc) * 16;
            uint32_t qh4[4], ql4[4];
            LDSM4(qh4[0], qh4[1], qh4[2], qh4[3], sQh + qoff);
            LDSM4(ql4[0], ql4[1], ql4[2], ql4[3], sQl + qoff);
            const int bck = 2 * ks + ((lane >> 3) & 1);
            uint32_t kh[4][4], kl[4][4];
#pragma unroll
            for (int p = 0; p < 4; p++) {
                const int krow = p * 16 + (lane & 7) + ((lane >> 4) << 3);
                uint32_t koff = krow * 256 + swz16(krow, bck) * 16;
                LDSM4(kh[p][0], kh[p][1], kh[p][2], kh[p][3], bKh + koff);
                LDSM4(kl[p][0], kl[p][1], kl[p][2], kl[p][3], bKl + koff);
            }
#pragma unroll
            for (int p = 0; p < 4; p++) {
                mma16816(s[2 * p],     qh4, kh[p] + 0);
                mma16816(s[2 * p + 1], qh4, kh[p] + 2);
                mma16816(s[2 * p],     qh4, kl[p] + 0);
                mma16816(s[2 * p + 1], qh4, kl[p] + 2);
                mma16816(s[2 * p],     ql4, kh[p] + 0);
                mma16816(s[2 * p + 1], ql4, kh[p] + 2);
            }
        }

        // ---- mask (skip for interior tiles)
        const bool need_mask = !((k0 + 63 <= q0 + R) && (k0 >= q0 + R - 1008));
        if (need_mask) {
#pragma unroll
            for (int j = 0; j < 8; j++) {
                int gj0 = k0 + j * 8 + cb, gj1 = gj0 + 1;
                if (gj0 > gi0 || gj0 + WIN <= gi0) s[j][0] = -1e30f;
                if (gj1 > gi0 || gj1 + WIN <= gi0) s[j][1] = -1e30f;
                if (gj0 > gi1 || gj0 + WIN <= gi1) s[j][2] = -1e30f;
                if (gj1 > gi1 || gj1 + WIN <= gi1) s[j][3] = -1e30f;
            }
        }

        // ---- online softmax
        float t0 = -1e30f, t1 = -1e30f;
#pragma unroll
        for (int j = 0; j < 8; j++) {
            t0 = fmaxf(t0, fmaxf(s[j][0], s[j][1]));
            t1 = fmaxf(t1, fmaxf(s[j][2], s[j][3]));
        }
        t0 = fmaxf(t0, __shfl_xor_sync(0xffffffffu, t0, 1));
        t0 = fmaxf(t0, __shfl_xor_sync(0xffffffffu, t0, 2));
        t1 = fmaxf(t1, __shfl_xor_sync(0xffffffffu, t1, 1));
        t1 = fmaxf(t1, __shfl_xor_sync(0xffffffffu, t1, 2));
        float mn0 = fmaxf(m0, t0), mn1 = fmaxf(m1, t1);
        float c0 = __expf(m0 - mn0), c1 = __expf(m1 - mn1);
        m0 = mn0; m1 = mn1;
        float rs0 = 0.0f, rs1 = 0.0f;
#pragma unroll
        for (int j = 0; j < 8; j++) {
            s[j][0] = __expf(s[j][0] - mn0); rs0 += s[j][0];
            s[j][1] = __expf(s[j][1] - mn0); rs0 += s[j][1];
            s[j][2] = __expf(s[j][2] - mn1); rs1 += s[j][2];
            s[j][3] = __expf(s[j][3] - mn1); rs1 += s[j][3];
        }
        rs0 += __shfl_xor_sync(0xffffffffu, rs0, 1);
        rs0 += __shfl_xor_sync(0xffffffffu, rs0, 2);
        rs1 += __shfl_xor_sync(0xffffffffu, rs1, 1);
        rs1 += __shfl_xor_sync(0xffffffffu, rs1, 2);
        l0 = l0 * c0 + rs0;
        l1 = l1 * c1 + rs1;
#pragma unroll
        for (int p = 0; p < 16; p++) {
            o[p][0] *= c0; o[p][1] *= c0;
            o[p][2] *= c1; o[p][3] *= c1;
        }

        // ---- P -> A fragments, hi/lo split
        uint32_t pah[4][4], pal[4][4];
#pragma unroll
        for (int ks2 = 0; ks2 < 4; ks2++) {
            int j = 2 * ks2;
            split2(s[j][0],     s[j][1],     pah[ks2][0], pal[ks2][0]);
            split2(s[j][2],     s[j][3],     pah[ks2][1], pal[ks2][1]);
            split2(s[j + 1][0], s[j + 1][1], pah[ks2][2], pal[ks2][2]);
            split2(s[j + 1][2], s[j + 1][3], pah[ks2][3], pal[ks2][3]);
        }

        // ---- O += P V: batch 8 LDSMs per 4-p group, then 24-MMA block
#pragma unroll
        for (int ks2 = 0; ks2 < 4; ks2++) {
            const int vck = 2 * ks2 + ((lane >> 3) & 1);
#pragma unroll
            for (int g = 0; g < 2; g++) {
                uint32_t vh[4][4], vl[4][4];
#pragma unroll
                for (int pp = 0; pp < 4; pp++) {
                    const int vrow = (g * 4 + pp) * 16 + (lane & 7) + ((lane >> 4) << 3);
                    uint32_t voff = vrow * 128 + swz8(vrow, vck) * 16;
                    LDSM4(vh[pp][0], vh[pp][1], vh[pp][2], vh[pp][3], bVh + voff);
                    LDSM4(vl[pp][0], vl[pp][1], vl[pp][2], vl[pp][3], bVl + voff);
                }
#pragma unroll
                for (int pp = 0; pp < 4; pp++) {
                    const int p = g * 4 + pp;
                    mma16816(o[2 * p],     pah[ks2], vh[pp] + 0);
                    mma16816(o[2 * p + 1], pah[ks2], vh[pp] + 2);
                    mma16816(o[2 * p],     pah[ks2], vl[pp] + 0);
                    mma16816(o[2 * p + 1], pah[ks2], vl[pp] + 2);
                    mma16816(o[2 * p],     pal[ks2], vh[pp] + 0);
                    mma16816(o[2 * p + 1], pal[ks2], vh[pp] + 2);
                }
            }
        }
        __syncthreads();
    }

    // ---- epilogue
    const float inv0 = 1.0f / l0;
    const float inv1 = 1.0f / l1;
#pragma unroll
    for (int p = 0; p < 16; p++) {
        int col = h * HD + p * 8 + cb;
        float2 v0 = { o[p][0] * inv0, o[p][1] * inv0 };
        float2 v1 = { o[p][2] * inv1, o[p][3] * inv1 };
        *(float2*)(g_a + (size_t)gi0 * DM + col) = v0;
        *(float2*)(g_a + (size_t)gi1 * DM + col) = v1;
    }
#undef PRE_KV
}

// ---------------------------------------------------------------------------
extern "C" void kernel_launch(void* const* d_in, const int* in_sizes, int n_in,
                              void* d_out, int out_size)
{
    (void)in_sizes; (void)n_in; (void)out_size;
    const float* x  = (const float*)d_in[0];
    const float* Wq = (const float*)d_in[1];
    const float* Wk = (const float*)d_in[2];
    const float* Wv = (const float*)d_in[3];
    const float* Wo = (const float*)d_in[4];
    float* out = (float*)d_out;

    cudaFuncSetAttribute(gemm_qkv, cudaFuncAttributeMaxDynamicSharedMemorySize, GEMM_SMEM);
    cudaFuncSetAttribute(gemm_wo,  cudaFuncAttributeMaxDynamicSharedMemorySize, GEMM_SMEM);
    cudaFuncSetAttribute(attn_mma, cudaFuncAttributeMaxDynamicSharedMemorySize, ATTN_SMEM);

    const int XB = (S_LEN * DM) / 1024;   // 8192
    const int WB = (DM * DM) / 1024;      // 16384

    split_x_kernel<<<XB, 256>>>(x);
    split_w_kernel<<<4 * WB, 256>>>(Wq, Wk, Wv, Wo);

    gemm_qkv<<<dim3(96, 16), 256, GEMM_SMEM>>>();

    rope_split_kernel<<<(S_LEN * NH * 64) / 256, 256>>>();
    vsplit_t_kernel<<<dim3(S_LEN / 32, DM / 32), 256>>>();

    attn_mma<<<dim3(S_LEN / 128, NH), 256, ATTN_SMEM>>>();

    split_a_kernel<<<XB, 256>>>();
    gemm_wo<<<dim3(DM / 128, S_LEN / 128), 256, GEMM_SMEM>>>(out);
}

// round 11
// speedup vs baseline: 3.4145x; 1.0115x over previous
#include <cuda_runtime.h>
#include <cuda_bf16.h>
#include <cstdint>

#define S_LEN 2048
#define DM    4096
#define NH    32
#define HD    128
#define WIN   1024

// ---------------- scratch (__device__ globals; no allocation APIs) ----------
__device__ float g_q[S_LEN * DM];
__device__ float g_k[S_LEN * DM];
__device__ float g_v[S_LEN * DM];

__device__ __nv_bfloat16 d_xh[S_LEN * DM], d_xl[S_LEN * DM];   // x split
__device__ __nv_bfloat16 d_ah[S_LEN * DM], d_al[S_LEN * DM];   // attn-out split
__device__ __nv_bfloat16 d_wh[4][DM * DM], d_wl[4][DM * DM];   // Wq,Wk,Wv,Wo

// attention operands (bf16 hi/lo)
__device__ __nv_bfloat16 d_qh[S_LEN * DM], d_ql[S_LEN * DM];   // Q (pre-scaled)
__device__ __nv_bfloat16 d_kh2[S_LEN * DM], d_kl2[S_LEN * DM]; // K
__device__ __nv_bfloat16 d_vth[S_LEN * DM], d_vtl[S_LEN * DM]; // V^T [h*128+d][s]

// ---------------- PTX helpers (sm_80-class only) ----------------------------
__device__ __forceinline__ uint32_t s2u(const void* p) {
    uint32_t r;
    asm("{ .reg .u64 t; cvta.to.shared.u64 t, %1; cvt.u32.u64 %0, t; }"
        : "=r"(r) : "l"(p));
    return r;
}
#define LDSM4(r0, r1, r2, r3, addr) \
    asm volatile("ldmatrix.sync.aligned.m8n8.x4.shared.b16 {%0,%1,%2,%3}, [%4];" \
        : "=r"(r0), "=r"(r1), "=r"(r2), "=r"(r3) : "r"(addr))
__device__ __forceinline__ void mma16816(float* c, const uint32_t* a, const uint32_t* b) {
    asm volatile(
        "mma.sync.aligned.m16n8k16.row.col.f32.bf16.bf16.f32 "
        "{%0,%1,%2,%3}, {%4,%5,%6,%7}, {%8,%9}, {%0,%1,%2,%3};"
        : "+f"(c[0]), "+f"(c[1]), "+f"(c[2]), "+f"(c[3])
        : "r"(a[0]), "r"(a[1]), "r"(a[2]), "r"(a[3]), "r"(b[0]), "r"(b[1]));
}
#define CPA16(dst, src) \
    asm volatile("cp.async.cg.shared.global [%0], [%1], 16;" :: "r"(dst), "l"(src))
#define CPC()  asm volatile("cp.async.commit_group;")
#define CPW2() asm volatile("cp.async.wait_group 2;")
#define CPW1() asm volatile("cp.async.wait_group 1;")
#define CPW0() asm volatile("cp.async.wait_group 0;")

// 16B-chunk XOR swizzles
__device__ __forceinline__ uint32_t tile_off(int row, int ck) {        // 4 chunks/row
    return (uint32_t)(((row << 2) + (ck ^ ((row >> 1) & 3))) << 4);
}
__device__ __forceinline__ uint32_t swz16(int r, int c) {              // 16 chunks/row
    return (uint32_t)((c & 8) | ((c ^ (r & 7)) & 7));
}
__device__ __forceinline__ uint32_t swz8(int r, int c) {               // 8 chunks/row
    return (uint32_t)(c ^ (r & 7));
}
__device__ __forceinline__ void split2(float x, float y, uint32_t& hi, uint32_t& lo) {
    __nv_bfloat16 hx = __float2bfloat16(x), hy = __float2bfloat16(y);
    __nv_bfloat162 hp = __halves2bfloat162(hx, hy);
    hi = *reinterpret_cast<uint32_t*>(&hp);
    __nv_bfloat16 lx = __float2bfloat16(x - __bfloat162float(hx));
    __nv_bfloat16 ly = __float2bfloat16(y - __bfloat162float(hy));
    __nv_bfloat162 lp = __halves2bfloat162(lx, ly);
    lo = *reinterpret_cast<uint32_t*>(&lp);
}

// ---------------------------------------------------------------------------
// Split fp32 -> bf16 hi/lo
// ---------------------------------------------------------------------------
__device__ __forceinline__ void split_body(const float* __restrict__ s,
                                           __nv_bfloat16* __restrict__ hi,
                                           __nv_bfloat16* __restrict__ lo, int i4)
{
    float4 v = ((const float4*)s)[i4];
    __nv_bfloat16 h0 = __float2bfloat16(v.x);
    __nv_bfloat16 h1 = __float2bfloat16(v.y);
    __nv_bfloat16 h2 = __float2bfloat16(v.z);
    __nv_bfloat16 h3 = __float2bfloat16(v.w);
    __nv_bfloat16 l0 = __float2bfloat16(v.x - __bfloat162float(h0));
    __nv_bfloat16 l1 = __float2bfloat16(v.y - __bfloat162float(h1));
    __nv_bfloat16 l2 = __float2bfloat16(v.z - __bfloat162float(h2));
    __nv_bfloat16 l3 = __float2bfloat16(v.w - __bfloat162float(h3));
    ((__nv_bfloat162*)hi)[i4 * 2 + 0] = __halves2bfloat162(h0, h1);
    ((__nv_bfloat162*)hi)[i4 * 2 + 1] = __halves2bfloat162(h2, h3);
    ((__nv_bfloat162*)lo)[i4 * 2 + 0] = __halves2bfloat162(l0, l1);
    ((__nv_bfloat162*)lo)[i4 * 2 + 1] = __halves2bfloat162(l2, l3);
}

__global__ void split_x_kernel(const float* __restrict__ src)   // x -> d_xh/d_xl
{
    int i4 = blockIdx.x * blockDim.x + threadIdx.x;
    split_body(src, d_xh, d_xl, i4);
}
// two weights per launch (keeps gemm_qkv at profiled launch index 3)
template <int BASE>
__global__ void split_w2_kernel(const float* __restrict__ Wa, const float* __restrict__ Wb)
{
    int w  = blockIdx.x >> 14;                 // 0 or 1
    int i4 = (blockIdx.x & 16383) * blockDim.x + threadIdx.x;
    const float* s = (w == 0) ? Wa : Wb;
    split_body(s, d_wh[BASE + w], d_wl[BASE + w], i4);
}

// ---------------------------------------------------------------------------
// mma.sync bf16-split GEMM body.  BM=BN=128, BK=32, 256 thr, 3-stage cp.async.
// ---------------------------------------------------------------------------
#define GEMM_SMEM (3 * 32768)

__device__ __forceinline__ void gemm_body(
    const __nv_bfloat16* __restrict__ Ah, const __nv_bfloat16* __restrict__ Al,
    const __nv_bfloat16* __restrict__ Bh, const __nv_bfloat16* __restrict__ Bl,
    float* __restrict__ C, int bm, int bn, uint32_t sb)
{
    const int tid  = threadIdx.x;
    const int lane = tid & 31;
    const int warp = tid >> 5;
    const int wm   = warp & 1;
    const int wn   = warp >> 1;

    float acc[16][4];
#pragma unroll
    for (int i = 0; i < 16; i++)
#pragma unroll
        for (int j = 0; j < 4; j++) acc[i][j] = 0.0f;

#define PREFETCH(kt, bi)                                                        \
    do {                                                                        \
        const int k0_ = (kt) * 32;                                              \
        const uint32_t bufb_ = sb + (bi) * 32768;                               \
        _Pragma("unroll")                                                       \
        for (int t_ = 0; t_ < 2; t_++) {                                        \
            int cid_ = tid + t_ * 256;                                          \
            int row_ = cid_ >> 2, ck_ = cid_ & 3;                               \
            uint32_t so_ = tile_off(row_, ck_);                                 \
            size_t ga_ = (size_t)(bm + row_) * DM + k0_ + ck_ * 8;              \
            size_t gb_ = (size_t)(bn + row_) * DM + k0_ + ck_ * 8;              \
            CPA16(bufb_ + so_,          Ah + ga_);                              \
            CPA16(bufb_ + 8192 + so_,   Al + ga_);                              \
            CPA16(bufb_ + 16384 + so_,  Bh + gb_);                              \
            CPA16(bufb_ + 24576 + so_,  Bl + gb_);                              \
        }                                                                       \
    } while (0)

    PREFETCH(0, 0); CPC();
    PREFETCH(1, 1); CPC();

    const int arow = (lane & 15) + wm * 64;
    const int acks = (lane >> 4);
    const int bnrw = wn * 32 + (lane & 7) + ((lane >> 4) << 3);
    const int bcks = ((lane >> 3) & 1);

    int bi = 0, bnext = 2;   // buffer of kt, buffer for kt+2
    for (int kt = 0; kt < 128; kt++) {
        if (kt + 2 < 128) {
            PREFETCH(kt + 2, bnext);
            CPC();
            CPW2();
        } else if (kt + 1 < 128) {
            CPW1();
        } else {
            CPW0();
        }
        __syncthreads();

        const uint32_t bAh = sb + bi * 32768;
        const uint32_t bAl = bAh + 8192;
        const uint32_t bBh = bAh + 16384;
        const uint32_t bBl = bAh + 24576;

#pragma unroll
        for (int s = 0; s < 2; s++) {
            uint32_t ah[4][4], al[4][4], bh[4][2], bl[4][2];
            const int ack = 2 * s + acks;
            const int bck = 2 * s + bcks;
#pragma unroll
            for (int mt = 0; mt < 4; mt++) {
                uint32_t off = tile_off(arow + mt * 16, ack);
                LDSM4(ah[mt][0], ah[mt][1], ah[mt][2], ah[mt][3], bAh + off);
                LDSM4(al[mt][0], al[mt][1], al[mt][2], al[mt][3], bAl + off);
            }
#pragma unroll
            for (int p = 0; p < 2; p++) {
                uint32_t off = tile_off(bnrw + p * 16, bck);
                uint32_t t0, t1, t2, t3;
                LDSM4(t0, t1, t2, t3, bBh + off);
                bh[2 * p][0] = t0; bh[2 * p][1] = t1;
                bh[2 * p + 1][0] = t2; bh[2 * p + 1][1] = t3;
                LDSM4(t0, t1, t2, t3, bBl + off);
                bl[2 * p][0] = t0; bl[2 * p][1] = t1;
                bl[2 * p + 1][0] = t2; bl[2 * p + 1][1] = t3;
            }
#pragma unroll
            for (int mt = 0; mt < 4; mt++)
#pragma unroll
                for (int nt = 0; nt < 4; nt++) {
                    mma16816(acc[mt * 4 + nt], ah[mt], bh[nt]);
                    mma16816(acc[mt * 4 + nt], ah[mt], bl[nt]);
                    mma16816(acc[mt * 4 + nt], al[mt], bh[nt]);
                }
        }
        __syncthreads();
        bi    = (bi    == 2) ? 0 : bi + 1;
        bnext = (bnext == 2) ? 0 : bnext + 1;
    }

#pragma unroll
    for (int mt = 0; mt < 4; mt++)
#pragma unroll
        for (int nt = 0; nt < 4; nt++) {
            int row = bm + wm * 64 + mt * 16 + (lane >> 2);
            int col = bn + wn * 32 + nt * 8 + 2 * (lane & 3);
            float* c0 = C + (size_t)row * DM + col;
            float* c1 = C + (size_t)(row + 8) * DM + col;
            float2 v0 = { acc[mt * 4 + nt][0], acc[mt * 4 + nt][1] };
            float2 v1 = { acc[mt * 4 + nt][2], acc[mt * 4 + nt][3] };
            *(float2*)c0 = v0;
            *(float2*)c1 = v1;
        }
#undef PREFETCH
}

// fused Q/K/V projection.  grid (16, 96): x = bm (fast) for L2-friendly waves,
// y picks weight + n-tile.
__global__ __launch_bounds__(256) void gemm_qkv()
{
    extern __shared__ __align__(16) char smraw[];
    const int which = blockIdx.y >> 5;            // 0,1,2
    const int bn    = (blockIdx.y & 31) * 128;
    const int bm    = blockIdx.x * 128;
    float* C = (which == 0) ? g_q : (which == 1) ? g_k : g_v;
    gemm_body(d_xh, d_xl, d_wh[which], d_wl[which], C, bm, bn, s2u(smraw));
}

// output projection.  grid (16, 32): x = bm (fast).
__global__ __launch_bounds__(256) void gemm_wo(float* __restrict__ out)
{
    extern __shared__ __align__(16) char smraw[];
    gemm_body(d_ah, d_al, d_wh[3], d_wl[3], out,
              blockIdx.x * 128, blockIdx.y * 128, s2u(smraw));
}

// ---------------------------------------------------------------------------
// RoPE + bf16 split (Q pre-scaled)
// ---------------------------------------------------------------------------
__global__ void rope_split_kernel()
{
    int idx = blockIdx.x * blockDim.x + threadIdx.x;
    int d = idx & 63;
    int s = idx >> 11;
    const float LOG2_10000 = 13.287712379549449f;
    const float SCALE = 0.08838834764831845f;
    float ex   = (float)(2 * d) * (1.0f / 128.0f);
    float invf = exp2f(-ex * LOG2_10000);
    float ang  = (float)s * invf;
    float cv = cosf(ang), sv = sinf(ang);
    int h = (idx >> 6) & 31;
    size_t base = (size_t)s * DM + h * HD + d;

    float q1 = g_q[base], q2 = g_q[base + 64];
    float qa = (q1 * cv - q2 * sv) * SCALE;
    float qb = (q2 * cv + q1 * sv) * SCALE;
    __nv_bfloat16 ha = __float2bfloat16(qa);
    __nv_bfloat16 hb = __float2bfloat16(qb);
    d_qh[base]      = ha; d_ql[base]      = __float2bfloat16(qa - __bfloat162float(ha));
    d_qh[base + 64] = hb; d_ql[base + 64] = __float2bfloat16(qb - __bfloat162float(hb));

    float k1 = g_k[base], k2 = g_k[base + 64];
    float ka = k1 * cv - k2 * sv;
    float kb = k2 * cv + k1 * sv;
    __nv_bfloat16 hc = __float2bfloat16(ka);
    __nv_bfloat16 hd_ = __float2bfloat16(kb);
    d_kh2[base]      = hc;  d_kl2[base]      = __float2bfloat16(ka - __bfloat162float(hc));
    d_kh2[base + 64] = hd_; d_kl2[base + 64] = __float2bfloat16(kb - __bfloat162float(hd_));
}

// ---------------------------------------------------------------------------
// V transpose + split
// ---------------------------------------------------------------------------
__global__ void vsplit_t_kernel()
{
    __shared__ float ts[32][33];
    const int bs = blockIdx.x * 32;
    const int bc = blockIdx.y * 32;
    const int tx = threadIdx.x & 31;
    const int ty = threadIdx.x >> 5;
#pragma unroll
    for (int i = 0; i < 4; i++) {
        int row = ty + i * 8;
        ts[row][tx] = g_v[(size_t)(bs + row) * DM + bc + tx];
    }
    __syncthreads();
#pragma unroll
    for (int i = 0; i < 4; i++) {
        int row = ty + i * 8;
        float v = ts[tx][row];
        __nv_bfloat16 hi = __float2bfloat16(v);
        size_t o = (size_t)(bc + row) * S_LEN + bs + tx;
        d_vth[o] = hi;
        d_vtl[o] = __float2bfloat16(v - __bfloat162float(hi));
    }
}

// ---------------------------------------------------------------------------
// Flash attention (R10 structure).  Epilogue fuses the hi/lo split for Wo.
// ---------------------------------------------------------------------------
#define ATTN_SMEM (65536 + 2 * 65536)   // 192 KB

__global__ __launch_bounds__(256, 1) void attn_mma()
{
    extern __shared__ __align__(16) char araw[];
    const uint32_t sb  = s2u(araw);
    const uint32_t sQh = sb, sQl = sb + 32768;

    const int qtb = (int)(gridDim.x - 1) - (int)blockIdx.x;
    const int h   = blockIdx.y;
    const int q0  = qtb * 128;
    const int tid = threadIdx.x;
    const int lane = tid & 31;
    const int warp = tid >> 5;
    const int R   = warp * 16;

#pragma unroll
    for (int t = 0; t < 8; t++) {
        int cid = tid + t * 256;
        int r = cid >> 4, c = cid & 15;
        size_t g = (size_t)(q0 + r) * DM + h * HD + c * 8;
        uint32_t so = r * 256 + swz16(r, c) * 16;
        CPA16(sQh + so, d_qh + g);
        CPA16(sQl + so, d_ql + g);
    }

#define PRE_KV(k0_, bi_)                                                        \
    do {                                                                        \
        const uint32_t bb_ = sb + 65536 + (bi_) * 65536;                        \
        _Pragma("unroll")                                                       \
        for (int t_ = 0; t_ < 4; t_++) {                                        \
            int cid_ = tid + t_ * 256;                                          \
            int kr_ = cid_ >> 4, kc_ = cid_ & 15;                               \
            size_t gk_ = (size_t)((k0_) + kr_) * DM + h * HD + kc_ * 8;         \
            uint32_t ko_ = kr_ * 256 + swz16(kr_, kc_) * 16;                    \
            CPA16(bb_ + ko_,         d_kh2 + gk_);                              \
            CPA16(bb_ + 16384 + ko_, d_kl2 + gk_);                              \
            int vr_ = cid_ >> 3, vc_ = cid_ & 7;                                \
            size_t gv_ = (size_t)(h * HD + vr_) * S_LEN + (k0_) + vc_ * 8;      \
            uint32_t vo_ = vr_ * 128 + swz8(vr_, vc_) * 16;                     \
            CPA16(bb_ + 32768 + vo_, d_vth + gv_);                              \
            CPA16(bb_ + 49152 + vo_, d_vtl + gv_);                              \
        }                                                                       \
    } while (0)

    int kb_lo = 2 * qtb - 16; if (kb_lo < 0) kb_lo = 0;
    const int niter = 2 * qtb + 1 - kb_lo + 1;

    PRE_KV(kb_lo * 64, 0);
    CPC();

    float m0 = -1e30f, m1 = -1e30f, l0 = 0.0f, l1 = 0.0f;
    float o[16][4];
#pragma unroll
    for (int p = 0; p < 16; p++)
#pragma unroll
        for (int j = 0; j < 4; j++) o[p][j] = 0.0f;

    const int r0  = lane >> 2;
    const int cb  = 2 * (lane & 3);
    const int gi0 = q0 + R + r0;
    const int gi1 = gi0 + 8;

    for (int it = 0; it < niter; it++) {
        const int k0 = (kb_lo + it) * 64;
        const int bi = it & 1;
        if (it + 1 < niter) {
            PRE_KV(k0 + 64, (it + 1) & 1);
            CPC();
            CPW1();
        } else {
            CPW0();
        }
        __syncthreads();

        const uint32_t bKh = sb + 65536 + bi * 65536;
        const uint32_t bKl = bKh + 16384;
        const uint32_t bVh = bKh + 32768;
        const uint32_t bVl = bKh + 49152;

        // ---- S = Q K^T
        float s[8][4];
#pragma unroll
        for (int j = 0; j < 8; j++)
#pragma unroll
            for (int e = 0; e < 4; e++) s[j][e] = 0.0f;

#pragma unroll
        for (int ks = 0; ks < 8; ks++) {
            const int qrow = R + (lane & 15);
            const int qc   = 2 * ks + (lane >> 4);
            uint32_t qoff  = qrow * 256 + swz16(qrow, qc) * 16;
            uint32_t qh4[4], ql4[4];
            LDSM4(qh4[0], qh4[1], qh4[2], qh4[3], sQh + qoff);
            LDSM4(ql4[0], ql4[1], ql4[2], ql4[3], sQl + qoff);
            const int bck = 2 * ks + ((lane >> 3) & 1);
            uint32_t kh[4][4], kl[4][4];
#pragma unroll
            for (int p = 0; p < 4; p++) {
                const int krow = p * 16 + (lane & 7) + ((lane >> 4) << 3);
                uint32_t koff = krow * 256 + swz16(krow, bck) * 16;
                LDSM4(kh[p][0], kh[p][1], kh[p][2], kh[p][3], bKh + koff);
                LDSM4(kl[p][0], kl[p][1], kl[p][2], kl[p][3], bKl + koff);
            }
#pragma unroll
            for (int p = 0; p < 4; p++) {
                mma16816(s[2 * p],     qh4, kh[p] + 0);
                mma16816(s[2 * p + 1], qh4, kh[p] + 2);
                mma16816(s[2 * p],     qh4, kl[p] + 0);
                mma16816(s[2 * p + 1], qh4, kl[p] + 2);
                mma16816(s[2 * p],     ql4, kh[p] + 0);
                mma16816(s[2 * p + 1], ql4, kh[p] + 2);
            }
        }

        // ---- mask (skip interior tiles)
        const bool need_mask = !((k0 + 63 <= q0 + R) && (k0 >= q0 + R - 1008));
        if (need_mask) {
#pragma unroll
            for (int j = 0; j < 8; j++) {
                int gj0 = k0 + j * 8 + cb, gj1 = gj0 + 1;
                if (gj0 > gi0 || gj0 + WIN <= gi0) s[j][0] = -1e30f;
                if (gj1 > gi0 || gj1 + WIN <= gi0) s[j][1] = -1e30f;
                if (gj0 > gi1 || gj0 + WIN <= gi1) s[j][2] = -1e30f;
                if (gj1 > gi1 || gj1 + WIN <= gi1) s[j][3] = -1e30f;
            }
        }

        // ---- online softmax
        float t0 = -1e30f, t1 = -1e30f;
#pragma unroll
        for (int j = 0; j < 8; j++) {
            t0 = fmaxf(t0, fmaxf(s[j][0], s[j][1]));
            t1 = fmaxf(t1, fmaxf(s[j][2], s[j][3]));
        }
        t0 = fmaxf(t0, __shfl_xor_sync(0xffffffffu, t0, 1));
        t0 = fmaxf(t0, __shfl_xor_sync(0xffffffffu, t0, 2));
        t1 = fmaxf(t1, __shfl_xor_sync(0xffffffffu, t1, 1));
        t1 = fmaxf(t1, __shfl_xor_sync(0xffffffffu, t1, 2));
        float mn0 = fmaxf(m0, t0), mn1 = fmaxf(m1, t1);
        float c0 = __expf(m0 - mn0), c1 = __expf(m1 - mn1);
        m0 = mn0; m1 = mn1;
        float rs0 = 0.0f, rs1 = 0.0f;
#pragma unroll
        for (int j = 0; j < 8; j++) {
            s[j][0] = __expf(s[j][0] - mn0); rs0 += s[j][0];
            s[j][1] = __expf(s[j][1] - mn0); rs0 += s[j][1];
            s[j][2] = __expf(s[j][2] - mn1); rs1 += s[j][2];
            s[j][3] = __expf(s[j][3] - mn1); rs1 += s[j][3];
        }
        rs0 += __shfl_xor_sync(0xffffffffu, rs0, 1);
        rs0 += __shfl_xor_sync(0xffffffffu, rs0, 2);
        rs1 += __shfl_xor_sync(0xffffffffu, rs1, 1);
        rs1 += __shfl_xor_sync(0xffffffffu, rs1, 2);
        l0 = l0 * c0 + rs0;
        l1 = l1 * c1 + rs1;
#pragma unroll
        for (int p = 0; p < 16; p++) {
            o[p][0] *= c0; o[p][1] *= c0;
            o[p][2] *= c1; o[p][3] *= c1;
        }

        // ---- P -> A fragments, hi/lo split
        uint32_t pah[4][4], pal[4][4];
#pragma unroll
        for (int ks2 = 0; ks2 < 4; ks2++) {
            int j = 2 * ks2;
            split2(s[j][0],     s[j][1],     pah[ks2][0], pal[ks2][0]);
            split2(s[j][2],     s[j][3],     pah[ks2][1], pal[ks2][1]);
            split2(s[j + 1][0], s[j + 1][1], pah[ks2][2], pal[ks2][2]);
            split2(s[j + 1][2], s[j + 1][3], pah[ks2][3], pal[ks2][3]);
        }

        // ---- O += P V
#pragma unroll
        for (int ks2 = 0; ks2 < 4; ks2++) {
            const int vck = 2 * ks2 + ((lane >> 3) & 1);
#pragma unroll
            for (int g = 0; g < 2; g++) {
                uint32_t vh[4][4], vl[4][4];
#pragma unroll
                for (int pp = 0; pp < 4; pp++) {
                    const int vrow = (g * 4 + pp) * 16 + (lane & 7) + ((lane >> 4) << 3);
                    uint32_t voff = vrow * 128 + swz8(vrow, vck) * 16;
                    LDSM4(vh[pp][0], vh[pp][1], vh[pp][2], vh[pp][3], bVh + voff);
                    LDSM4(vl[pp][0], vl[pp][1], vl[pp][2], vl[pp][3], bVl + voff);
                }
#pragma unroll
                for (int pp = 0; pp < 4; pp++) {
                    const int p = g * 4 + pp;
                    mma16816(o[2 * p],     pah[ks2], vh[pp] + 0);
                    mma16816(o[2 * p + 1], pah[ks2], vh[pp] + 2);
                    mma16816(o[2 * p],     pah[ks2], vl[pp] + 0);
                    mma16816(o[2 * p + 1], pah[ks2], vl[pp] + 2);
                    mma16816(o[2 * p],     pal[ks2], vh[pp] + 0);
                    mma16816(o[2 * p + 1], pal[ks2], vh[pp] + 2);
                }
            }
        }
        __syncthreads();
    }

    // ---- epilogue: normalize + fused hi/lo split (feeds gemm_wo directly)
    const float inv0 = 1.0f / l0;
    const float inv1 = 1.0f / l1;
#pragma unroll
    for (int p = 0; p < 16; p++) {
        int col = h * HD + p * 8 + cb;
        uint32_t hi, lo;
        split2(o[p][0] * inv0, o[p][1] * inv0, hi, lo);
        *(uint32_t*)(d_ah + (size_t)gi0 * DM + col) = hi;
        *(uint32_t*)(d_al + (size_t)gi0 * DM + col) = lo;
        split2(o[p][2] * inv1, o[p][3] * inv1, hi, lo);
        *(uint32_t*)(d_ah + (size_t)gi1 * DM + col) = hi;
        *(uint32_t*)(d_al + (size_t)gi1 * DM + col) = lo;
    }
#undef PRE_KV
}

// ---------------------------------------------------------------------------
extern "C" void kernel_launch(void* const* d_in, const int* in_sizes, int n_in,
                              void* d_out, int out_size)
{
    (void)in_sizes; (void)n_in; (void)out_size;
    const float* x  = (const float*)d_in[0];
    const float* Wq = (const float*)d_in[1];
    const float* Wk = (const float*)d_in[2];
    const float* Wv = (const float*)d_in[3];
    const float* Wo = (const float*)d_in[4];
    float* out = (float*)d_out;

    cudaFuncSetAttribute(gemm_qkv, cudaFuncAttributeMaxDynamicSharedMemorySize, GEMM_SMEM);
    cudaFuncSetAttribute(gemm_wo,  cudaFuncAttributeMaxDynamicSharedMemorySize, GEMM_SMEM);
    cudaFuncSetAttribute(attn_mma, cudaFuncAttributeMaxDynamicSharedMemorySize, ATTN_SMEM);

    const int XB = (S_LEN * DM) / 1024;   // 8192
    const int WB = (DM * DM) / 1024;      // 16384

    split_x_kernel<<<XB, 256>>>(x);                       // launch 0
    split_w2_kernel<0><<<2 * WB, 256>>>(Wq, Wk);          // launch 1
    split_w2_kernel<2><<<2 * WB, 256>>>(Wv, Wo);          // launch 2

    gemm_qkv<<<dim3(16, 96), 256, GEMM_SMEM>>>();         // launch 3 (profiled)

    rope_split_kernel<<<(S_LEN * NH * 64) / 256, 256>>>();
    vsplit_t_kernel<<<dim3(S_LEN / 32, DM / 32), 256>>>();

    attn_mma<<<dim3(S_LEN / 128, NH), 256, ATTN_SMEM>>>();

    gemm_wo<<<dim3(16, 32), 256, GEMM_SMEM>>>(out);
}

// round 12
// speedup vs baseline: 3.4264x; 1.0035x over previous
#include <cuda_runtime.h>
#include <cuda_bf16.h>
#include <cstdint>

#define S_LEN 2048
#define DM    4096
#define NH    32
#define HD    128
#define WIN   1024

// ---------------- scratch (__device__ globals; no allocation APIs) ----------
__device__ __nv_bfloat16 d_xh[S_LEN * DM], d_xl[S_LEN * DM];   // x split
__device__ __nv_bfloat16 d_ah[S_LEN * DM], d_al[S_LEN * DM];   // attn-out split
__device__ __nv_bfloat16 d_wh[4][DM * DM], d_wl[4][DM * DM];   // Wq,Wk,Wv,Wo

// attention operands (bf16 hi/lo)
__device__ __nv_bfloat16 d_qh[S_LEN * DM], d_ql[S_LEN * DM];   // Q (pre-scaled)
__device__ __nv_bfloat16 d_kh2[S_LEN * DM], d_kl2[S_LEN * DM]; // K
__device__ __nv_bfloat16 d_vth[S_LEN * DM], d_vtl[S_LEN * DM]; // V^T [h*128+d][s]

// ---------------- PTX helpers (sm_80-class only) ----------------------------
__device__ __forceinline__ uint32_t s2u(const void* p) {
    uint32_t r;
    asm("{ .reg .u64 t; cvta.to.shared.u64 t, %1; cvt.u32.u64 %0, t; }"
        : "=r"(r) : "l"(p));
    return r;
}
#define LDSM4(r0, r1, r2, r3, addr) \
    asm volatile("ldmatrix.sync.aligned.m8n8.x4.shared.b16 {%0,%1,%2,%3}, [%4];" \
        : "=r"(r0), "=r"(r1), "=r"(r2), "=r"(r3) : "r"(addr))
__device__ __forceinline__ void mma16816(float* c, const uint32_t* a, const uint32_t* b) {
    asm volatile(
        "mma.sync.aligned.m16n8k16.row.col.f32.bf16.bf16.f32 "
        "{%0,%1,%2,%3}, {%4,%5,%6,%7}, {%8,%9}, {%0,%1,%2,%3};"
        : "+f"(c[0]), "+f"(c[1]), "+f"(c[2]), "+f"(c[3])
        : "r"(a[0]), "r"(a[1]), "r"(a[2]), "r"(a[3]), "r"(b[0]), "r"(b[1]));
}
#define CPA16(dst, src) \
    asm volatile("cp.async.cg.shared.global [%0], [%1], 16;" :: "r"(dst), "l"(src))
#define CPC()  asm volatile("cp.async.commit_group;")
#define CPW2() asm volatile("cp.async.wait_group 2;")
#define CPW1() asm volatile("cp.async.wait_group 1;")
#define CPW0() asm volatile("cp.async.wait_group 0;")

// 16B-chunk XOR swizzles
__device__ __forceinline__ uint32_t tile_off(int row, int ck) {        // 4 chunks/row
    return (uint32_t)(((row << 2) + (ck ^ ((row >> 1) & 3))) << 4);
}
__device__ __forceinline__ uint32_t swz16(int r, int c) {              // 16 chunks/row
    return (uint32_t)((c & 8) | ((c ^ (r & 7)) & 7));
}
__device__ __forceinline__ uint32_t swz8(int r, int c) {               // 8 chunks/row
    return (uint32_t)(c ^ (r & 7));
}
__device__ __forceinline__ void split2(float x, float y, uint32_t& hi, uint32_t& lo) {
    __nv_bfloat16 hx = __float2bfloat16(x), hy = __float2bfloat16(y);
    __nv_bfloat162 hp = __halves2bfloat162(hx, hy);
    hi = *reinterpret_cast<uint32_t*>(&hp);
    __nv_bfloat16 lx = __float2bfloat16(x - __bfloat162float(hx));
    __nv_bfloat16 ly = __float2bfloat16(y - __bfloat162float(hy));
    __nv_bfloat162 lp = __halves2bfloat162(lx, ly);
    lo = *reinterpret_cast<uint32_t*>(&lp);
}

// ---------------------------------------------------------------------------
// Split fp32 -> bf16 hi/lo
// ---------------------------------------------------------------------------
__device__ __forceinline__ void split_body(const float* __restrict__ s,
                                           __nv_bfloat16* __restrict__ hi,
                                           __nv_bfloat16* __restrict__ lo, int i4)
{
    float4 v = ((const float4*)s)[i4];
    __nv_bfloat16 h0 = __float2bfloat16(v.x);
    __nv_bfloat16 h1 = __float2bfloat16(v.y);
    __nv_bfloat16 h2 = __float2bfloat16(v.z);
    __nv_bfloat16 h3 = __float2bfloat16(v.w);
    __nv_bfloat16 l0 = __float2bfloat16(v.x - __bfloat162float(h0));
    __nv_bfloat16 l1 = __float2bfloat16(v.y - __bfloat162float(h1));
    __nv_bfloat16 l2 = __float2bfloat16(v.z - __bfloat162float(h2));
    __nv_bfloat16 l3 = __float2bfloat16(v.w - __bfloat162float(h3));
    ((__nv_bfloat162*)hi)[i4 * 2 + 0] = __halves2bfloat162(h0, h1);
    ((__nv_bfloat162*)hi)[i4 * 2 + 1] = __halves2bfloat162(h2, h3);
    ((__nv_bfloat162*)lo)[i4 * 2 + 0] = __halves2bfloat162(l0, l1);
    ((__nv_bfloat162*)lo)[i4 * 2 + 1] = __halves2bfloat162(l2, l3);
}

__global__ void split_x_kernel(const float* __restrict__ src)   // x -> d_xh/d_xl
{
    int i4 = blockIdx.x * blockDim.x + threadIdx.x;
    split_body(src, d_xh, d_xl, i4);
}
// all four weights in one launch: grid = 4 * 16384
__global__ void split_w_kernel(const float* __restrict__ Wq, const float* __restrict__ Wk,
                               const float* __restrict__ Wv, const float* __restrict__ Wo)
{
    int w  = blockIdx.x >> 14;
    int i4 = (blockIdx.x & 16383) * blockDim.x + threadIdx.x;
    const float* s = (w == 0) ? Wq : (w == 1) ? Wk : (w == 2) ? Wv : Wo;
    split_body(s, d_wh[w], d_wl[w], i4);
}

// ---------------------------------------------------------------------------
// mma.sync bf16-split GEMM mainloop.  BM=BN=128, BK=32, 256 thr, 3-stage.
// Leaves result in acc[16][4]; caller does the epilogue.  Ends synced.
// ---------------------------------------------------------------------------
#define GEMM_SMEM (3 * 32768)

__device__ __forceinline__ void gemm_mainloop(
    const __nv_bfloat16* __restrict__ Ah, const __nv_bfloat16* __restrict__ Al,
    const __nv_bfloat16* __restrict__ Bh, const __nv_bfloat16* __restrict__ Bl,
    int bm, int bn, uint32_t sb, float acc[16][4])
{
    const int tid  = threadIdx.x;
    const int lane = tid & 31;
    const int warp = tid >> 5;
    const int wm   = warp & 1;
    const int wn   = warp >> 1;

#pragma unroll
    for (int i = 0; i < 16; i++)
#pragma unroll
        for (int j = 0; j < 4; j++) acc[i][j] = 0.0f;

#define PREFETCH(kt, bi)                                                        \
    do {                                                                        \
        const int k0_ = (kt) * 32;                                              \
        const uint32_t bufb_ = sb + (bi) * 32768;                               \
        _Pragma("unroll")                                                       \
        for (int t_ = 0; t_ < 2; t_++) {                                        \
            int cid_ = tid + t_ * 256;                                          \
            int row_ = cid_ >> 2, ck_ = cid_ & 3;                               \
            uint32_t so_ = tile_off(row_, ck_);                                 \
            size_t ga_ = (size_t)(bm + row_) * DM + k0_ + ck_ * 8;              \
            size_t gb_ = (size_t)(bn + row_) * DM + k0_ + ck_ * 8;              \
            CPA16(bufb_ + so_,          Ah + ga_);                              \
            CPA16(bufb_ + 8192 + so_,   Al + ga_);                              \
            CPA16(bufb_ + 16384 + so_,  Bh + gb_);                              \
            CPA16(bufb_ + 24576 + so_,  Bl + gb_);                              \
        }                                                                       \
    } while (0)

    PREFETCH(0, 0); CPC();
    PREFETCH(1, 1); CPC();

    const int arow = (lane & 15) + wm * 64;
    const int acks = (lane >> 4);
    const int bnrw = wn * 32 + (lane & 7) + ((lane >> 4) << 3);
    const int bcks = ((lane >> 3) & 1);

    int bi = 0, bnext = 2;
    for (int kt = 0; kt < 128; kt++) {
        if (kt + 2 < 128) {
            PREFETCH(kt + 2, bnext);
            CPC();
            CPW2();
        } else if (kt + 1 < 128) {
            CPW1();
        } else {
            CPW0();
        }
        __syncthreads();

        const uint32_t bAh = sb + bi * 32768;
        const uint32_t bAl = bAh + 8192;
        const uint32_t bBh = bAh + 16384;
        const uint32_t bBl = bAh + 24576;

#pragma unroll
        for (int s = 0; s < 2; s++) {
            uint32_t ah[4][4], al[4][4], bh[4][2], bl[4][2];
            const int ack = 2 * s + acks;
            const int bck = 2 * s + bcks;
#pragma unroll
            for (int mt = 0; mt < 4; mt++) {
                uint32_t off = tile_off(arow + mt * 16, ack);
                LDSM4(ah[mt][0], ah[mt][1], ah[mt][2], ah[mt][3], bAh + off);
                LDSM4(al[mt][0], al[mt][1], al[mt][2], al[mt][3], bAl + off);
            }
#pragma unroll
            for (int p = 0; p < 2; p++) {
                uint32_t off = tile_off(bnrw + p * 16, bck);
                uint32_t t0, t1, t2, t3;
                LDSM4(t0, t1, t2, t3, bBh + off);
                bh[2 * p][0] = t0; bh[2 * p][1] = t1;
                bh[2 * p + 1][0] = t2; bh[2 * p + 1][1] = t3;
                LDSM4(t0, t1, t2, t3, bBl + off);
                bl[2 * p][0] = t0; bl[2 * p][1] = t1;
                bl[2 * p + 1][0] = t2; bl[2 * p + 1][1] = t3;
            }
#pragma unroll
            for (int mt = 0; mt < 4; mt++)
#pragma unroll
                for (int nt = 0; nt < 4; nt++) {
                    mma16816(acc[mt * 4 + nt], ah[mt], bh[nt]);
                    mma16816(acc[mt * 4 + nt], ah[mt], bl[nt]);
                    mma16816(acc[mt * 4 + nt], al[mt], bh[nt]);
                }
        }
        __syncthreads();
        bi    = (bi    == 2) ? 0 : bi + 1;
        bnext = (bnext == 2) ? 0 : bnext + 1;
    }
#undef PREFETCH
}

// ---------------------------------------------------------------------------
// Fused Q/K/V projection + RoPE/scale/split (Q,K) or transpose/split (V).
// grid (16, 96): x = bm (fast, L2-friendly), y = weight*32 + n-tile.
// Epilogue stages acc in smem (fp32, stride 130) and writes bf16 hi/lo.
// ---------------------------------------------------------------------------
__global__ __launch_bounds__(256, 2) void gemm_qkv()
{
    extern __shared__ __align__(16) char smraw[];
    const int which = blockIdx.y >> 5;            // 0=Q,1=K,2=V
    const int bn    = (blockIdx.y & 31) * 128;
    const int bm    = blockIdx.x * 128;

    float acc[16][4];
    gemm_mainloop(d_xh, d_xl, d_wh[which], d_wl[which], bm, bn, s2u(smraw), acc);

    // stage acc tile -> smem fp32 [128][130]
    float* smf = (float*)smraw;
    const int lane = threadIdx.x & 31;
    const int warp = threadIdx.x >> 5;
    const int wm = warp & 1, wn = warp >> 1;
#pragma unroll
    for (int mt = 0; mt < 4; mt++)
#pragma unroll
        for (int nt = 0; nt < 4; nt++) {
            int r = wm * 64 + mt * 16 + (lane >> 2);
            int c = wn * 32 + nt * 8 + 2 * (lane & 3);
            float2 v0 = { acc[mt * 4 + nt][0], acc[mt * 4 + nt][1] };
            float2 v1 = { acc[mt * 4 + nt][2], acc[mt * 4 + nt][3] };
            *(float2*)&smf[r * 130 + c]       = v0;
            *(float2*)&smf[(r + 8) * 130 + c] = v1;
        }
    __syncthreads();

    if (which == 2) {
        // V: transposed split write  d_vt*[bn+c][bm+s]
#pragma unroll 8
        for (int i = 0; i < 64; i++) {
            int idx = i * 256 + threadIdx.x;
            int c = idx >> 7, s = idx & 127;
            float v = smf[s * 130 + c];
            __nv_bfloat16 hi = __float2bfloat16(v);
            size_t o = (size_t)(bn + c) * S_LEN + bm + s;
            d_vth[o] = hi;
            d_vtl[o] = __float2bfloat16(v - __bfloat162float(hi));
        }
    } else {
        // Q/K: RoPE (+scale for Q) + split
        __nv_bfloat16* oh = which ? d_kh2 : d_qh;
        __nv_bfloat16* ol = which ? d_kl2 : d_ql;
        const float sc = which ? 1.0f : 0.08838834764831845f;
        const float LOG2_10000 = 13.287712379549449f;
#pragma unroll 8
        for (int p = 0; p < 32; p++) {
            int pid = p * 256 + threadIdx.x;
            int row = pid >> 6, d = pid & 63;
            int sg = bm + row;
            float ex   = (float)(2 * d) * (1.0f / 128.0f);
            float invf = exp2f(-ex * LOG2_10000);
            float ang  = (float)sg * invf;
            float cv = cosf(ang), sv = sinf(ang);
            float a = smf[row * 130 + d], b = smf[row * 130 + d + 64];
            float ra = (a * cv - b * sv) * sc;
            float rb = (b * cv + a * sv) * sc;
            __nv_bfloat16 h1 = __float2bfloat16(ra);
            __nv_bfloat16 h2 = __float2bfloat16(rb);
            size_t o1 = (size_t)sg * DM + bn + d;
            oh[o1]      = h1;
            ol[o1]      = __float2bfloat16(ra - __bfloat162float(h1));
            oh[o1 + 64] = h2;
            ol[o1 + 64] = __float2bfloat16(rb - __bfloat162float(h2));
        }
    }
}

// ---------------------------------------------------------------------------
// Output projection.  grid (16, 32): x = bm (fast).  Plain fp32 epilogue.
// ---------------------------------------------------------------------------
__global__ __launch_bounds__(256, 2) void gemm_wo(float* __restrict__ out)
{
    extern __shared__ __align__(16) char smraw[];
    const int bm = blockIdx.x * 128;
    const int bn = blockIdx.y * 128;

    float acc[16][4];
    gemm_mainloop(d_ah, d_al, d_wh[3], d_wl[3], bm, bn, s2u(smraw), acc);

    const int lane = threadIdx.x & 31;
    const int warp = threadIdx.x >> 5;
    const int wm = warp & 1, wn = warp >> 1;
#pragma unroll
    for (int mt = 0; mt < 4; mt++)
#pragma unroll
        for (int nt = 0; nt < 4; nt++) {
            int row = bm + wm * 64 + mt * 16 + (lane >> 2);
            int col = bn + wn * 32 + nt * 8 + 2 * (lane & 3);
            float2 v0 = { acc[mt * 4 + nt][0], acc[mt * 4 + nt][1] };
            float2 v1 = { acc[mt * 4 + nt][2], acc[mt * 4 + nt][3] };
            *(float2*)(out + (size_t)row * DM + col)       = v0;
            *(float2*)(out + (size_t)(row + 8) * DM + col) = v1;
        }
}

// ---------------------------------------------------------------------------
// Flash attention (R11 structure, unchanged).  Epilogue emits split d_ah/d_al.
// ---------------------------------------------------------------------------
#define ATTN_SMEM (65536 + 2 * 65536)   // 192 KB

__global__ __launch_bounds__(256, 1) void attn_mma()
{
    extern __shared__ __align__(16) char araw[];
    const uint32_t sb  = s2u(araw);
    const uint32_t sQh = sb, sQl = sb + 32768;

    const int qtb = (int)(gridDim.x - 1) - (int)blockIdx.x;
    const int h   = blockIdx.y;
    const int q0  = qtb * 128;
    const int tid = threadIdx.x;
    const int lane = tid & 31;
    const int warp = tid >> 5;
    const int R   = warp * 16;

#pragma unroll
    for (int t = 0; t < 8; t++) {
        int cid = tid + t * 256;
        int r = cid >> 4, c = cid & 15;
        size_t g = (size_t)(q0 + r) * DM + h * HD + c * 8;
        uint32_t so = r * 256 + swz16(r, c) * 16;
        CPA16(sQh + so, d_qh + g);
        CPA16(sQl + so, d_ql + g);
    }

#define PRE_KV(k0_, bi_)                                                        \
    do {                                                                        \
        const uint32_t bb_ = sb + 65536 + (bi_) * 65536;                        \
        _Pragma("unroll")                                                       \
        for (int t_ = 0; t_ < 4; t_++) {                                        \
            int cid_ = tid + t_ * 256;                                          \
            int kr_ = cid_ >> 4, kc_ = cid_ & 15;                               \
            size_t gk_ = (size_t)((k0_) + kr_) * DM + h * HD + kc_ * 8;         \
            uint32_t ko_ = kr_ * 256 + swz16(kr_, kc_) * 16;                    \
            CPA16(bb_ + ko_,         d_kh2 + gk_);                              \
            CPA16(bb_ + 16384 + ko_, d_kl2 + gk_);                              \
            int vr_ = cid_ >> 3, vc_ = cid_ & 7;                                \
            size_t gv_ = (size_t)(h * HD + vr_) * S_LEN + (k0_) + vc_ * 8;      \
            uint32_t vo_ = vr_ * 128 + swz8(vr_, vc_) * 16;                     \
            CPA16(bb_ + 32768 + vo_, d_vth + gv_);                              \
            CPA16(bb_ + 49152 + vo_, d_vtl + gv_);                              \
        }                                                                       \
    } while (0)

    int kb_lo = 2 * qtb - 16; if (kb_lo < 0) kb_lo = 0;
    const int niter = 2 * qtb + 1 - kb_lo + 1;

    PRE_KV(kb_lo * 64, 0);
    CPC();

    float m0 = -1e30f, m1 = -1e30f, l0 = 0.0f, l1 = 0.0f;
    float o[16][4];
#pragma unroll
    for (int p = 0; p < 16; p++)
#pragma unroll
        for (int j = 0; j < 4; j++) o[p][j] = 0.0f;

    const int r0  = lane >> 2;
    const int cb  = 2 * (lane & 3);
    const int gi0 = q0 + R + r0;
    const int gi1 = gi0 + 8;

    for (int it = 0; it < niter; it++) {
        const int k0 = (kb_lo + it) * 64;
        const int bi = it & 1;
        if (it + 1 < niter) {
            PRE_KV(k0 + 64, (it + 1) & 1);
            CPC();
            CPW1();
        } else {
            CPW0();
        }
        __syncthreads();

        const uint32_t bKh = sb + 65536 + bi * 65536;
        const uint32_t bKl = bKh + 16384;
        const uint32_t bVh = bKh + 32768;
        const uint32_t bVl = bKh + 49152;

        // ---- S = Q K^T
        float s[8][4];
#pragma unroll
        for (int j = 0; j < 8; j++)
#pragma unroll
            for (int e = 0; e < 4; e++) s[j][e] = 0.0f;

#pragma unroll
        for (int ks = 0; ks < 8; ks++) {
            const int qrow = R + (lane & 15);
            const int qc   = 2 * ks + (lane >> 4);
            uint32_t qoff  = qrow * 256 + swz16(qrow, qc) * 16;
            uint32_t qh4[4], ql4[4];
            LDSM4(qh4[0], qh4[1], qh4[2], qh4[3], sQh + qoff);
            LDSM4(ql4[0], ql4[1], ql4[2], ql4[3], sQl + qoff);
            const int bck = 2 * ks + ((lane >> 3) & 1);
            uint32_t kh[4][4], kl[4][4];
#pragma unroll
            for (int p = 0; p < 4; p++) {
                const int krow = p * 16 + (lane & 7) + ((lane >> 4) << 3);
                uint32_t koff = krow * 256 + swz16(krow, bck) * 16;
                LDSM4(kh[p][0], kh[p][1], kh[p][2], kh[p][3], bKh + koff);
                LDSM4(kl[p][0], kl[p][1], kl[p][2], kl[p][3], bKl + koff);
            }
#pragma unroll
            for (int p = 0; p < 4; p++) {
                mma16816(s[2 * p],     qh4, kh[p] + 0);
                mma16816(s[2 * p + 1], qh4, kh[p] + 2);
                mma16816(s[2 * p],     qh4, kl[p] + 0);
                mma16816(s[2 * p + 1], qh4, kl[p] + 2);
                mma16816(s[2 * p],     ql4, kh[p] + 0);
                mma16816(s[2 * p + 1], ql4, kh[p] + 2);
            }
        }

        // ---- mask (skip interior tiles)
        const bool need_mask = !((k0 + 63 <= q0 + R) && (k0 >= q0 + R - 1008));
        if (need_mask) {
#pragma unroll
            for (int j = 0; j < 8; j++) {
                int gj0 = k0 + j * 8 + cb, gj1 = gj0 + 1;
                if (gj0 > gi0 || gj0 + WIN <= gi0) s[j][0] = -1e30f;
                if (gj1 > gi0 || gj1 + WIN <= gi0) s[j][1] = -1e30f;
                if (gj0 > gi1 || gj0 + WIN <= gi1) s[j][2] = -1e30f;
                if (gj1 > gi1 || gj1 + WIN <= gi1) s[j][3] = -1e30f;
            }
        }

        // ---- online softmax
        float t0 = -1e30f, t1 = -1e30f;
#pragma unroll
        for (int j = 0; j < 8; j++) {
            t0 = fmaxf(t0, fmaxf(s[j][0], s[j][1]));
            t1 = fmaxf(t1, fmaxf(s[j][2], s[j][3]));
        }
        t0 = fmaxf(t0, __shfl_xor_sync(0xffffffffu, t0, 1));
        t0 = fmaxf(t0, __shfl_xor_sync(0xffffffffu, t0, 2));
        t1 = fmaxf(t1, __shfl_xor_sync(0xffffffffu, t1, 1));
        t1 = fmaxf(t1, __shfl_xor_sync(0xffffffffu, t1, 2));
        float mn0 = fmaxf(m0, t0), mn1 = fmaxf(m1, t1);
        float c0 = __expf(m0 - mn0), c1 = __expf(m1 - mn1);
        m0 = mn0; m1 = mn1;
        float rs0 = 0.0f, rs1 = 0.0f;
#pragma unroll
        for (int j = 0; j < 8; j++) {
            s[j][0] = __expf(s[j][0] - mn0); rs0 += s[j][0];
            s[j][1] = __expf(s[j][1] - mn0); rs0 += s[j][1];
            s[j][2] = __expf(s[j][2] - mn1); rs1 += s[j][2];
            s[j][3] = __expf(s[j][3] - mn1); rs1 += s[j][3];
        }
        rs0 += __shfl_xor_sync(0xffffffffu, rs0, 1);
        rs0 += __shfl_xor_sync(0xffffffffu, rs0, 2);
        rs1 += __shfl_xor_sync(0xffffffffu, rs1, 1);
        rs1 += __shfl_xor_sync(0xffffffffu, rs1, 2);
        l0 = l0 * c0 + rs0;
        l1 = l1 * c1 + rs1;
#pragma unroll
        for (int p = 0; p < 16; p++) {
            o[p][0] *= c0; o[p][1] *= c0;
            o[p][2] *= c1; o[p][3] *= c1;
        }

        // ---- P -> A fragments, hi/lo split
        uint32_t pah[4][4], pal[4][4];
#pragma unroll
        for (int ks2 = 0; ks2 < 4; ks2++) {
            int j = 2 * ks2;
            split2(s[j][0],     s[j][1],     pah[ks2][0], pal[ks2][0]);
            split2(s[j][2],     s[j][3],     pah[ks2][1], pal[ks2][1]);
            split2(s[j + 1][0], s[j + 1][1], pah[ks2][2], pal[ks2][2]);
            split2(s[j + 1][2], s[j + 1][3], pah[ks2][3], pal[ks2][3]);
        }

        // ---- O += P V
#pragma unroll
        for (int ks2 = 0; ks2 < 4; ks2++) {
            const int vck = 2 * ks2 + ((lane >> 3) & 1);
#pragma unroll
            for (int g = 0; g < 2; g++) {
                uint32_t vh[4][4], vl[4][4];
#pragma unroll
                for (int pp = 0; pp < 4; pp++) {
                    const int vrow = (g * 4 + pp) * 16 + (lane & 7) + ((lane >> 4) << 3);
                    uint32_t voff = vrow * 128 + swz8(vrow, vck) * 16;
                    LDSM4(vh[pp][0], vh[pp][1], vh[pp][2], vh[pp][3], bVh + voff);
                    LDSM4(vl[pp][0], vl[pp][1], vl[pp][2], vl[pp][3], bVl + voff);
                }
#pragma unroll
                for (int pp = 0; pp < 4; pp++) {
                    const int p = g * 4 + pp;
                    mma16816(o[2 * p],     pah[ks2], vh[pp] + 0);
                    mma16816(o[2 * p + 1], pah[ks2], vh[pp] + 2);
                    mma16816(o[2 * p],     pah[ks2], vl[pp] + 0);
                    mma16816(o[2 * p + 1], pah[ks2], vl[pp] + 2);
                    mma16816(o[2 * p],     pal[ks2], vh[pp] + 0);
                    mma16816(o[2 * p + 1], pal[ks2], vh[pp] + 2);
                }
            }
        }
        __syncthreads();
    }

    // ---- epilogue: normalize + fused hi/lo split (feeds gemm_wo directly)
    const float inv0 = 1.0f / l0;
    const float inv1 = 1.0f / l1;
#pragma unroll
    for (int p = 0; p < 16; p++) {
        int col = h * HD + p * 8 + cb;
        uint32_t hi, lo;
        split2(o[p][0] * inv0, o[p][1] * inv0, hi, lo);
        *(uint32_t*)(d_ah + (size_t)gi0 * DM + col) = hi;
        *(uint32_t*)(d_al + (size_t)gi0 * DM + col) = lo;
        split2(o[p][2] * inv1, o[p][3] * inv1, hi, lo);
        *(uint32_t*)(d_ah + (size_t)gi1 * DM + col) = hi;
        *(uint32_t*)(d_al + (size_t)gi1 * DM + col) = lo;
    }
#undef PRE_KV
}

// ---------------------------------------------------------------------------
extern "C" void kernel_launch(void* const* d_in, const int* in_sizes, int n_in,
                              void* d_out, int out_size)
{
    (void)in_sizes; (void)n_in; (void)out_size;
    const float* x  = (const float*)d_in[0];
    const float* Wq = (const float*)d_in[1];
    const float* Wk = (const float*)d_in[2];
    const float* Wv = (const float*)d_in[3];
    const float* Wo = (const float*)d_in[4];
    float* out = (float*)d_out;

    cudaFuncSetAttribute(gemm_qkv, cudaFuncAttributeMaxDynamicSharedMemorySize, GEMM_SMEM);
    cudaFuncSetAttribute(gemm_wo,  cudaFuncAttributeMaxDynamicSharedMemorySize, GEMM_SMEM);
    cudaFuncSetAttribute(attn_mma, cudaFuncAttributeMaxDynamicSharedMemorySize, ATTN_SMEM);

    const int XB = (S_LEN * DM) / 1024;   // 8192
    const int WB = (DM * DM) / 1024;      // 16384

    split_x_kernel<<<XB, 256>>>(x);                       // launch 0
    split_w_kernel<<<4 * WB, 256>>>(Wq, Wk, Wv, Wo);      // launch 1

    gemm_qkv<<<dim3(16, 96), 256, GEMM_SMEM>>>();         // launch 2

    attn_mma<<<dim3(S_LEN / 128, NH), 256, ATTN_SMEM>>>();// launch 3 (profiled)

    gemm_wo<<<dim3(16, 32), 256, GEMM_SMEM>>>(out);       // launch 4
}

// round 13
// speedup vs baseline: 3.4462x; 1.0058x over previous
#include <cuda_runtime.h>
#include <cuda_bf16.h>
#include <cstdint>

#define S_LEN 2048
#define DM    4096
#define NH    32
#define HD    128
#define WIN   1024

// ---------------- scratch (__device__ globals; no allocation APIs) ----------
__device__ __nv_bfloat16 d_xh[S_LEN * DM], d_xl[S_LEN * DM];   // x split
__device__ __nv_bfloat16 d_ah[S_LEN * DM], d_al[S_LEN * DM];   // attn-out split
__device__ __nv_bfloat16 d_wh[4][DM * DM], d_wl[4][DM * DM];   // Wq,Wk,Wv,Wo

// attention operands (bf16 hi/lo)
__device__ __nv_bfloat16 d_qh[S_LEN * DM], d_ql[S_LEN * DM];   // Q (pre-scaled)
__device__ __nv_bfloat16 d_kh2[S_LEN * DM], d_kl2[S_LEN * DM]; // K
__device__ __nv_bfloat16 d_vth[S_LEN * DM], d_vtl[S_LEN * DM]; // V^T [h*128+d][s]

// ---------------- PTX helpers (sm_80-class only) ----------------------------
__device__ __forceinline__ uint32_t s2u(const void* p) {
    uint32_t r;
    asm("{ .reg .u64 t; cvta.to.shared.u64 t, %1; cvt.u32.u64 %0, t; }"
        : "=r"(r) : "l"(p));
    return r;
}
#define LDSM4(r0, r1, r2, r3, addr) \
    asm volatile("ldmatrix.sync.aligned.m8n8.x4.shared.b16 {%0,%1,%2,%3}, [%4];" \
        : "=r"(r0), "=r"(r1), "=r"(r2), "=r"(r3) : "r"(addr))
__device__ __forceinline__ void mma16816(float* c, const uint32_t* a, const uint32_t* b) {
    asm volatile(
        "mma.sync.aligned.m16n8k16.row.col.f32.bf16.bf16.f32 "
        "{%0,%1,%2,%3}, {%4,%5,%6,%7}, {%8,%9}, {%0,%1,%2,%3};"
        : "+f"(c[0]), "+f"(c[1]), "+f"(c[2]), "+f"(c[3])
        : "r"(a[0]), "r"(a[1]), "r"(a[2]), "r"(a[3]), "r"(b[0]), "r"(b[1]));
}
#define CPA16(dst, src) \
    asm volatile("cp.async.cg.shared.global [%0], [%1], 16;" :: "r"(dst), "l"(src))
#define CPC()  asm volatile("cp.async.commit_group;")
#define CPW1() asm volatile("cp.async.wait_group 1;")
#define CPW0() asm volatile("cp.async.wait_group 0;")

// 16B-chunk XOR swizzles
__device__ __forceinline__ uint32_t tile_off(int row, int ck) {        // 4 chunks/row
    return (uint32_t)(((row << 2) + (ck ^ ((row >> 1) & 3))) << 4);
}
__device__ __forceinline__ uint32_t swz16(int r, int c) {              // 16 chunks/row
    return (uint32_t)((c & 8) | ((c ^ (r & 7)) & 7));
}
__device__ __forceinline__ uint32_t swz8(int r, int c) {               // 8 chunks/row
    return (uint32_t)(c ^ (r & 7));
}
__device__ __forceinline__ void split2(float x, float y, uint32_t& hi, uint32_t& lo) {
    __nv_bfloat16 hx = __float2bfloat16(x), hy = __float2bfloat16(y);
    __nv_bfloat162 hp = __halves2bfloat162(hx, hy);
    hi = *reinterpret_cast<uint32_t*>(&hp);
    __nv_bfloat16 lx = __float2bfloat16(x - __bfloat162float(hx));
    __nv_bfloat16 ly = __float2bfloat16(y - __bfloat162float(hy));
    __nv_bfloat162 lp = __halves2bfloat162(lx, ly);
    lo = *reinterpret_cast<uint32_t*>(&lp);
}

// ---------------------------------------------------------------------------
// Split fp32 -> bf16 hi/lo
// ---------------------------------------------------------------------------
__device__ __forceinline__ void split_body(const float* __restrict__ s,
                                           __nv_bfloat16* __restrict__ hi,
                                           __nv_bfloat16* __restrict__ lo, int i4)
{
    float4 v = ((const float4*)s)[i4];
    __nv_bfloat16 h0 = __float2bfloat16(v.x);
    __nv_bfloat16 h1 = __float2bfloat16(v.y);
    __nv_bfloat16 h2 = __float2bfloat16(v.z);
    __nv_bfloat16 h3 = __float2bfloat16(v.w);
    __nv_bfloat16 l0 = __float2bfloat16(v.x - __bfloat162float(h0));
    __nv_bfloat16 l1 = __float2bfloat16(v.y - __bfloat162float(h1));
    __nv_bfloat16 l2 = __float2bfloat16(v.z - __bfloat162float(h2));
    __nv_bfloat16 l3 = __float2bfloat16(v.w - __bfloat162float(h3));
    ((__nv_bfloat162*)hi)[i4 * 2 + 0] = __halves2bfloat162(h0, h1);
    ((__nv_bfloat162*)hi)[i4 * 2 + 1] = __halves2bfloat162(h2, h3);
    ((__nv_bfloat162*)lo)[i4 * 2 + 0] = __halves2bfloat162(l0, l1);
    ((__nv_bfloat162*)lo)[i4 * 2 + 1] = __halves2bfloat162(l2, l3);
}

__global__ void split_x_kernel(const float* __restrict__ src)   // x -> d_xh/d_xl
{
    int i4 = blockIdx.x * blockDim.x + threadIdx.x;
    split_body(src, d_xh, d_xl, i4);
}
// all four weights in one launch: grid = 4 * 16384
__global__ void split_w_kernel(const float* __restrict__ Wq, const float* __restrict__ Wk,
                               const float* __restrict__ Wv, const float* __restrict__ Wo)
{
    int w  = blockIdx.x >> 14;
    int i4 = (blockIdx.x & 16383) * blockDim.x + threadIdx.x;
    const float* s = (w == 0) ? Wq : (w == 1) ? Wk : (w == 2) ? Wv : Wo;
    split_body(s, d_wh[w], d_wl[w], i4);
}

// ---------------------------------------------------------------------------
// mma.sync bf16-split GEMM mainloop.  BM=BN=128, BK=32, 256 thr, 3-stage,
// SINGLE __syncthreads per kt (prefetch issued after the barrier: target
// buffer (kt+2)%3 == (kt-1)%3 was consumed by all warps before the barrier).
// Ends with a trailing sync so callers may reuse smem.
// ---------------------------------------------------------------------------
#define GEMM_SMEM (3 * 32768)

__device__ __forceinline__ void gemm_mainloop(
    const __nv_bfloat16* __restrict__ Ah, const __nv_bfloat16* __restrict__ Al,
    const __nv_bfloat16* __restrict__ Bh, const __nv_bfloat16* __restrict__ Bl,
    int bm, int bn, uint32_t sb, float acc[16][4])
{
    const int tid  = threadIdx.x;
    const int lane = tid & 31;
    const int warp = tid >> 5;
    const int wm   = warp & 1;
    const int wn   = warp >> 1;

#pragma unroll
    for (int i = 0; i < 16; i++)
#pragma unroll
        for (int j = 0; j < 4; j++) acc[i][j] = 0.0f;

#define PREFETCH(kt, bi)                                                        \
    do {                                                                        \
        const int k0_ = (kt) * 32;                                              \
        const uint32_t bufb_ = sb + (bi) * 32768;                               \
        _Pragma("unroll")                                                       \
        for (int t_ = 0; t_ < 2; t_++) {                                        \
            int cid_ = tid + t_ * 256;                                          \
            int row_ = cid_ >> 2, ck_ = cid_ & 3;                               \
            uint32_t so_ = tile_off(row_, ck_);                                 \
            size_t ga_ = (size_t)(bm + row_) * DM + k0_ + ck_ * 8;              \
            size_t gb_ = (size_t)(bn + row_) * DM + k0_ + ck_ * 8;              \
            CPA16(bufb_ + so_,          Ah + ga_);                              \
            CPA16(bufb_ + 8192 + so_,   Al + ga_);                              \
            CPA16(bufb_ + 16384 + so_,  Bh + gb_);                              \
            CPA16(bufb_ + 24576 + so_,  Bl + gb_);                              \
        }                                                                       \
    } while (0)

    PREFETCH(0, 0); CPC();
    PREFETCH(1, 1); CPC();

    const int arow = (lane & 15) + wm * 64;
    const int acks = (lane >> 4);
    const int bnrw = wn * 32 + (lane & 7) + ((lane >> 4) << 3);
    const int bcks = ((lane >> 3) & 1);

    int bi = 0, bnext = 2;
    for (int kt = 0; kt < 128; kt++) {
        // group kt must be complete; groups kt+1 (and later, after PF below)
        // may remain outstanding.
        if (kt < 127) { CPW1(); } else { CPW0(); }
        __syncthreads();
        if (kt + 2 < 128) {
            PREFETCH(kt + 2, bnext);   // safe: all warps consumed this buffer at kt-1
            CPC();
        }

        const uint32_t bAh = sb + bi * 32768;
        const uint32_t bAl = bAh + 8192;
        const uint32_t bBh = bAh + 16384;
        const uint32_t bBl = bAh + 24576;

#pragma unroll
        for (int s = 0; s < 2; s++) {
            uint32_t ah[4][4], al[4][4], bh[4][2], bl[4][2];
            const int ack = 2 * s + acks;
            const int bck = 2 * s + bcks;
#pragma unroll
            for (int mt = 0; mt < 4; mt++) {
                uint32_t off = tile_off(arow + mt * 16, ack);
                LDSM4(ah[mt][0], ah[mt][1], ah[mt][2], ah[mt][3], bAh + off);
                LDSM4(al[mt][0], al[mt][1], al[mt][2], al[mt][3], bAl + off);
            }
#pragma unroll
            for (int p = 0; p < 2; p++) {
                uint32_t off = tile_off(bnrw + p * 16, bck);
                uint32_t t0, t1, t2, t3;
                LDSM4(t0, t1, t2, t3, bBh + off);
                bh[2 * p][0] = t0; bh[2 * p][1] = t1;
                bh[2 * p + 1][0] = t2; bh[2 * p + 1][1] = t3;
                LDSM4(t0, t1, t2, t3, bBl + off);
                bl[2 * p][0] = t0; bl[2 * p][1] = t1;
                bl[2 * p + 1][0] = t2; bl[2 * p + 1][1] = t3;
            }
#pragma unroll
            for (int mt = 0; mt < 4; mt++)
#pragma unroll
                for (int nt = 0; nt < 4; nt++) {
                    mma16816(acc[mt * 4 + nt], ah[mt], bh[nt]);
                    mma16816(acc[mt * 4 + nt], ah[mt], bl[nt]);
                    mma16816(acc[mt * 4 + nt], al[mt], bh[nt]);
                }
        }
        bi    = (bi    == 2) ? 0 : bi + 1;
        bnext = (bnext == 2) ? 0 : bnext + 1;
    }
    __syncthreads();   // callers reuse smem right after
#undef PREFETCH
}

// ---------------------------------------------------------------------------
// Fused Q/K/V projection + RoPE/scale/split (Q,K) or transpose/split (V).
// grid (16, 96): x = bm (fast, L2-friendly), y = weight*32 + n-tile.
// ---------------------------------------------------------------------------
__global__ __launch_bounds__(256, 2) void gemm_qkv()
{
    extern __shared__ __align__(16) char smraw[];
    const int which = blockIdx.y >> 5;            // 0=Q,1=K,2=V
    const int bn    = (blockIdx.y & 31) * 128;
    const int bm    = blockIdx.x * 128;

    float acc[16][4];
    gemm_mainloop(d_xh, d_xl, d_wh[which], d_wl[which], bm, bn, s2u(smraw), acc);

    // stage acc tile -> smem fp32 [128][130]
    float* smf = (float*)smraw;
    const int lane = threadIdx.x & 31;
    const int warp = threadIdx.x >> 5;
    const int wm = warp & 1, wn = warp >> 1;
#pragma unroll
    for (int mt = 0; mt < 4; mt++)
#pragma unroll
        for (int nt = 0; nt < 4; nt++) {
            int r = wm * 64 + mt * 16 + (lane >> 2);
            int c = wn * 32 + nt * 8 + 2 * (lane & 3);
            float2 v0 = { acc[mt * 4 + nt][0], acc[mt * 4 + nt][1] };
            float2 v1 = { acc[mt * 4 + nt][2], acc[mt * 4 + nt][3] };
            *(float2*)&smf[r * 130 + c]       = v0;
            *(float2*)&smf[(r + 8) * 130 + c] = v1;
        }
    __syncthreads();

    if (which == 2) {
        // V: transposed split write  d_vt*[bn+c][bm+s]
#pragma unroll 8
        for (int i = 0; i < 64; i++) {
            int idx = i * 256 + threadIdx.x;
            int c = idx >> 7, s = idx & 127;
            float v = smf[s * 130 + c];
            __nv_bfloat16 hi = __float2bfloat16(v);
            size_t o = (size_t)(bn + c) * S_LEN + bm + s;
            d_vth[o] = hi;
            d_vtl[o] = __float2bfloat16(v - __bfloat162float(hi));
        }
    } else {
        // Q/K: RoPE (+scale for Q) + split
        __nv_bfloat16* oh = which ? d_kh2 : d_qh;
        __nv_bfloat16* ol = which ? d_kl2 : d_ql;
        const float sc = which ? 1.0f : 0.08838834764831845f;
        const float LOG2_10000 = 13.287712379549449f;
#pragma unroll 8
        for (int p = 0; p < 32; p++) {
            int pid = p * 256 + threadIdx.x;
            int row = pid >> 6, d = pid & 63;
            int sg = bm + row;
            float ex   = (float)(2 * d) * (1.0f / 128.0f);
            float invf = exp2f(-ex * LOG2_10000);
            float ang  = (float)sg * invf;
            float cv = cosf(ang), sv = sinf(ang);
            float a = smf[row * 130 + d], b = smf[row * 130 + d + 64];
            float ra = (a * cv - b * sv) * sc;
            float rb = (b * cv + a * sv) * sc;
            __nv_bfloat16 h1 = __float2bfloat16(ra);
            __nv_bfloat16 h2 = __float2bfloat16(rb);
            size_t o1 = (size_t)sg * DM + bn + d;
            oh[o1]      = h1;
            ol[o1]      = __float2bfloat16(ra - __bfloat162float(h1));
            oh[o1 + 64] = h2;
            ol[o1 + 64] = __float2bfloat16(rb - __bfloat162float(h2));
        }
    }
}

// ---------------------------------------------------------------------------
// Output projection.  grid (16, 32): x = bm (fast).  Plain fp32 epilogue.
// ---------------------------------------------------------------------------
__global__ __launch_bounds__(256, 2) void gemm_wo(float* __restrict__ out)
{
    extern __shared__ __align__(16) char smraw[];
    const int bm = blockIdx.x * 128;
    const int bn = blockIdx.y * 128;

    float acc[16][4];
    gemm_mainloop(d_ah, d_al, d_wh[3], d_wl[3], bm, bn, s2u(smraw), acc);

    const int lane = threadIdx.x & 31;
    const int warp = threadIdx.x >> 5;
    const int wm = warp & 1, wn = warp >> 1;
#pragma unroll
    for (int mt = 0; mt < 4; mt++)
#pragma unroll
        for (int nt = 0; nt < 4; nt++) {
            int row = bm + wm * 64 + mt * 16 + (lane >> 2);
            int col = bn + wn * 32 + nt * 8 + 2 * (lane & 3);
            float2 v0 = { acc[mt * 4 + nt][0], acc[mt * 4 + nt][1] };
            float2 v1 = { acc[mt * 4 + nt][2], acc[mt * 4 + nt][3] };
            *(float2*)(out + (size_t)row * DM + col)       = v0;
            *(float2*)(out + (size_t)(row + 8) * DM + col) = v1;
        }
}

// ---------------------------------------------------------------------------
// Flash attention (R12 structure, unchanged).
// ---------------------------------------------------------------------------
#define ATTN_SMEM (65536 + 2 * 65536)   // 192 KB

__global__ __launch_bounds__(256, 1) void attn_mma()
{
    extern __shared__ __align__(16) char araw[];
    const uint32_t sb  = s2u(araw);
    const uint32_t sQh = sb, sQl = sb + 32768;

    const int qtb = (int)(gridDim.x - 1) - (int)blockIdx.x;
    const int h   = blockIdx.y;
    const int q0  = qtb * 128;
    const int tid = threadIdx.x;
    const int lane = tid & 31;
    const int warp = tid >> 5;
    const int R   = warp * 16;

#pragma unroll
    for (int t = 0; t < 8; t++) {
        int cid = tid + t * 256;
        int r = cid >> 4, c = cid & 15;
        size_t g = (size_t)(q0 + r) * DM + h * HD + c * 8;
        uint32_t so = r * 256 + swz16(r, c) * 16;
        CPA16(sQh + so, d_qh + g);
        CPA16(sQl + so, d_ql + g);
    }

#define PRE_KV(k0_, bi_)                                                        \
    do {                                                                        \
        const uint32_t bb_ = sb + 65536 + (bi_) * 65536;                        \
        _Pragma("unroll")                                                       \
        for (int t_ = 0; t_ < 4; t_++) {                                        \
            int cid_ = tid + t_ * 256;                                          \
            int kr_ = cid_ >> 4, kc_ = cid_ & 15;                               \
            size_t gk_ = (size_t)((k0_) + kr_) * DM + h * HD + kc_ * 8;         \
            uint32_t ko_ = kr_ * 256 + swz16(kr_, kc_) * 16;                    \
            CPA16(bb_ + ko_,         d_kh2 + gk_);                              \
            CPA16(bb_ + 16384 + ko_, d_kl2 + gk_);                              \
            int vr_ = cid_ >> 3, vc_ = cid_ & 7;                                \
            size_t gv_ = (size_t)(h * HD + vr_) * S_LEN + (k0_) + vc_ * 8;      \
            uint32_t vo_ = vr_ * 128 + swz8(vr_, vc_) * 16;                     \
            CPA16(bb_ + 32768 + vo_, d_vth + gv_);                              \
            CPA16(bb_ + 49152 + vo_, d_vtl + gv_);                              \
        }                                                                       \
    } while (0)

    int kb_lo = 2 * qtb - 16; if (kb_lo < 0) kb_lo = 0;
    const int niter = 2 * qtb + 1 - kb_lo + 1;

    PRE_KV(kb_lo * 64, 0);
    CPC();

    float m0 = -1e30f, m1 = -1e30f, l0 = 0.0f, l1 = 0.0f;
    float o[16][4];
#pragma unroll
    for (int p = 0; p < 16; p++)
#pragma unroll
        for (int j = 0; j < 4; j++) o[p][j] = 0.0f;

    const int r0  = lane >> 2;
    const int cb  = 2 * (lane & 3);
    const int gi0 = q0 + R + r0;
    const int gi1 = gi0 + 8;

    for (int it = 0; it < niter; it++) {
        const int k0 = (kb_lo + it) * 64;
        const int bi = it & 1;
        if (it + 1 < niter) {
            PRE_KV(k0 + 64, (it + 1) & 1);
            CPC();
            CPW1();
        } else {
            CPW0();
        }
        __syncthreads();

        const uint32_t bKh = sb + 65536 + bi * 65536;
        const uint32_t bKl = bKh + 16384;
        const uint32_t bVh = bKh + 32768;
        const uint32_t bVl = bKh + 49152;

        // ---- S = Q K^T
        float s[8][4];
#pragma unroll
        for (int j = 0; j < 8; j++)
#pragma unroll
            for (int e = 0; e < 4; e++) s[j][e] = 0.0f;

#pragma unroll
        for (int ks = 0; ks < 8; ks++) {
            const int qrow = R + (lane & 15);
            const int qc   = 2 * ks + (lane >> 4);
            uint32_t qoff  = qrow * 256 + swz16(qrow, qc) * 16;
            uint32_t qh4[4], ql4[4];
            LDSM4(qh4[0], qh4[1], qh4[2], qh4[3], sQh + qoff);
            LDSM4(ql4[0], ql4[1], ql4[2], ql4[3], sQl + qoff);
            const int bck = 2 * ks + ((lane >> 3) & 1);
            uint32_t kh[4][4], kl[4][4];
#pragma unroll
            for (int p = 0; p < 4; p++) {
                const int krow = p * 16 + (lane & 7) + ((lane >> 4) << 3);
                uint32_t koff = krow * 256 + swz16(krow, bck) * 16;
                LDSM4(kh[p][0], kh[p][1], kh[p][2], kh[p][3], bKh + koff);
                LDSM4(kl[p][0], kl[p][1], kl[p][2], kl[p][3], bKl + koff);
            }
#pragma unroll
            for (int p = 0; p < 4; p++) {
                mma16816(s[2 * p],     qh4, kh[p] + 0);
                mma16816(s[2 * p + 1], qh4, kh[p] + 2);
                mma16816(s[2 * p],     qh4, kl[p] + 0);
                mma16816(s[2 * p + 1], qh4, kl[p] + 2);
                mma16816(s[2 * p],     ql4, kh[p] + 0);
                mma16816(s[2 * p + 1], ql4, kh[p] + 2);
            }
        }

        // ---- mask (skip interior tiles)
        const bool need_mask = !((k0 + 63 <= q0 + R) && (k0 >= q0 + R - 1008));
        if (need_mask) {
#pragma unroll
            for (int j = 0; j < 8; j++) {
                int gj0 = k0 + j * 8 + cb, gj1 = gj0 + 1;
                if (gj0 > gi0 || gj0 + WIN <= gi0) s[j][0] = -1e30f;
                if (gj1 > gi0 || gj1 + WIN <= gi0) s[j][1] = -1e30f;
                if (gj0 > gi1 || gj0 + WIN <= gi1) s[j][2] = -1e30f;
                if (gj1 > gi1 || gj1 + WIN <= gi1) s[j][3] = -1e30f;
            }
        }

        // ---- online softmax
        float t0 = -1e30f, t1 = -1e30f;
#pragma unroll
        for (int j = 0; j < 8; j++) {
            t0 = fmaxf(t0, fmaxf(s[j][0], s[j][1]));
            t1 = fmaxf(t1, fmaxf(s[j][2], s[j][3]));
        }
        t0 = fmaxf(t0, __shfl_xor_sync(0xffffffffu, t0, 1));
        t0 = fmaxf(t0, __shfl_xor_sync(0xffffffffu, t0, 2));
        t1 = fmaxf(t1, __shfl_xor_sync(0xffffffffu, t1, 1));
        t1 = fmaxf(t1, __shfl_xor_sync(0xffffffffu, t1, 2));
        float mn0 = fmaxf(m0, t0), mn1 = fmaxf(m1, t1);
        float c0 = __expf(m0 - mn0), c1 = __expf(m1 - mn1);
        m0 = mn0; m1 = mn1;
        float rs0 = 0.0f, rs1 = 0.0f;
#pragma unroll
        for (int j = 0; j < 8; j++) {
            s[j][0] = __expf(s[j][0] - mn0); rs0 += s[j][0];
            s[j][1] = __expf(s[j][1] - mn0); rs0 += s[j][1];
            s[j][2] = __expf(s[j][2] - mn1); rs1 += s[j][2];
            s[j][3] = __expf(s[j][3] - mn1); rs1 += s[j][3];
        }
        rs0 += __shfl_xor_sync(0xffffffffu, rs0, 1);
        rs0 += __shfl_xor_sync(0xffffffffu, rs0, 2);
        rs1 += __shfl_xor_sync(0xffffffffu, rs1, 1);
        rs1 += __shfl_xor_sync(0xffffffffu, rs1, 2);
        l0 = l0 * c0 + rs0;
        l1 = l1 * c1 + rs1;
#pragma unroll
        for (int p = 0; p < 16; p++) {
            o[p][0] *= c0; o[p][1] *= c0;
            o[p][2] *= c1; o[p][3] *= c1;
        }

        // ---- P -> A fragments, hi/lo split
        uint32_t pah[4][4], pal[4][4];
#pragma unroll
        for (int ks2 = 0; ks2 < 4; ks2++) {
            int j = 2 * ks2;
            split2(s[j][0],     s[j][1],     pah[ks2][0], pal[ks2][0]);
            split2(s[j][2],     s[j][3],     pah[ks2][1], pal[ks2][1]);
            split2(s[j + 1][0], s[j + 1][1], pah[ks2][2], pal[ks2][2]);
            split2(s[j + 1][2], s[j + 1][3], pah[ks2][3], pal[ks2][3]);
        }

        // ---- O += P V
#pragma unroll
        for (int ks2 = 0; ks2 < 4; ks2++) {
            const int vck = 2 * ks2 + ((lane >> 3) & 1);
#pragma unroll
            for (int g = 0; g < 2; g++) {
                uint32_t vh[4][4], vl[4][4];
#pragma unroll
                for (int pp = 0; pp < 4; pp++) {
                    const int vrow = (g * 4 + pp) * 16 + (lane & 7) + ((lane >> 4) << 3);
                    uint32_t voff = vrow * 128 + swz8(vrow, vck) * 16;
                    LDSM4(vh[pp][0], vh[pp][1], vh[pp][2], vh[pp][3], bVh + voff);
                    LDSM4(vl[pp][0], vl[pp][1], vl[pp][2], vl[pp][3], bVl + voff);
                }
#pragma unroll
                for (int pp = 0; pp < 4; pp++) {
                    const int p = g * 4 + pp;
                    mma16816(o[2 * p],     pah[ks2], vh[pp] + 0);
                    mma16816(o[2 * p + 1], pah[ks2], vh[pp] + 2);
                    mma16816(o[2 * p],     pah[ks2], vl[pp] + 0);
                    mma16816(o[2 * p + 1], pah[ks2], vl[pp] + 2);
                    mma16816(o[2 * p],     pal[ks2], vh[pp] + 0);
                    mma16816(o[2 * p + 1], pal[ks2], vh[pp] + 2);
                }
            }
        }
        __syncthreads();
    }

    // ---- epilogue: normalize + fused hi/lo split (feeds gemm_wo directly)
    const float inv0 = 1.0f / l0;
    const float inv1 = 1.0f / l1;
#pragma unroll
    for (int p = 0; p < 16; p++) {
        int col = h * HD + p * 8 + cb;
        uint32_t hi, lo;
        split2(o[p][0] * inv0, o[p][1] * inv0, hi, lo);
        *(uint32_t*)(d_ah + (size_t)gi0 * DM + col) = hi;
        *(uint32_t*)(d_al + (size_t)gi0 * DM + col) = lo;
        split2(o[p][2] * inv1, o[p][3] * inv1, hi, lo);
        *(uint32_t*)(d_ah + (size_t)gi1 * DM + col) = hi;
        *(uint32_t*)(d_al + (size_t)gi1 * DM + col) = lo;
    }
#undef PRE_KV
}

// ---------------------------------------------------------------------------
extern "C" void kernel_launch(void* const* d_in, const int* in_sizes, int n_in,
                              void* d_out, int out_size)
{
    (void)in_sizes; (void)n_in; (void)out_size;
    const float* x  = (const float*)d_in[0];
    const float* Wq = (const float*)d_in[1];
    const float* Wk = (const float*)d_in[2];
    const float* Wv = (const float*)d_in[3];
    const float* Wo = (const float*)d_in[4];
    float* out = (float*)d_out;

    cudaFuncSetAttribute(gemm_qkv, cudaFuncAttributeMaxDynamicSharedMemorySize, GEMM_SMEM);
    cudaFuncSetAttribute(gemm_wo,  cudaFuncAttributeMaxDynamicSharedMemorySize, GEMM_SMEM);
    cudaFuncSetAttribute(attn_mma, cudaFuncAttributeMaxDynamicSharedMemorySize, ATTN_SMEM);

    const int XB = (S_LEN * DM) / 1024;   // 8192
    const int WB = (DM * DM) / 1024;      // 16384

    split_x_kernel<<<XB, 256>>>(x);                       // launch 0
    split_w_kernel<<<4 * WB, 256>>>(Wq, Wk, Wv, Wo);      // launch 1

    gemm_qkv<<<dim3(16, 96), 256, GEMM_SMEM>>>();         // launch 2

    attn_mma<<<dim3(S_LEN / 128, NH), 256, ATTN_SMEM>>>();// launch 3 (profiled)

    gemm_wo<<<dim3(16, 32), 256, GEMM_SMEM>>>(out);       // launch 4
}